// round 11
// baseline (speedup 1.0000x reference)
#include <cuda_runtime.h>
#include <math.h>

#define NN 50000
#define EE 400000
#define FF 128
#define HH 8
#define CC 64
#define BB 64
#define KK 10
#define HC (HH*CC)     /* 512 */
#define ETOT (EE+NN)   /* 450000 edges incl. self loops */

// ---------------- scratch (device globals; no allocation allowed) ----------------
__device__ __align__(16) float g_h1[(size_t)NN*HC];    // x@W1
__device__ __align__(16) float g_out1[(size_t)NN*HC];  // elu(gat1)
__device__ __align__(16) float g_h2[(size_t)NN*CC];    // out1@W2
__device__ __align__(16) float g_out2[(size_t)NN*CC];  // elu(gat2)
__device__ __align__(16) float g_as1[NN*HH];
__device__ __align__(16) float g_ad1[NN*HH];
__device__ __align__(16) float g_as2[NN];
__device__ __align__(16) float g_ad2[NN];
__device__ __align__(16) float g_pooled[BB*CC];
__device__ __align__(16) float g_As1[FF*HH];   // W1 contracted with att_src1
__device__ __align__(16) float g_Ad1[FF*HH];   // W1 contracted with att_dst1
__device__ int g_deg[NN];
__device__ int g_rowptr[NN+1];
__device__ int g_fill[NN];
__device__ int g_csr[ETOT];

// ---------------- f32x2 packed helpers (Blackwell FFMA2) ----------------
__device__ __forceinline__ unsigned long long pk2(float lo, float hi) {
    unsigned long long r;
    asm("mov.b64 %0, {%1, %2};" : "=l"(r) : "r"(__float_as_uint(lo)), "r"(__float_as_uint(hi)));
    return r;
}
__device__ __forceinline__ void unpk2(unsigned long long v, float& lo, float& hi) {
    unsigned int a, b;
    asm("mov.b64 {%0, %1}, %2;" : "=r"(a), "=r"(b) : "l"(v));
    lo = __uint_as_float(a); hi = __uint_as_float(b);
}
__device__ __forceinline__ unsigned long long ffma2(unsigned long long a,
                                                    unsigned long long b,
                                                    unsigned long long c) {
    unsigned long long d;
    asm("fma.rn.f32x2 %0, %1, %2, %3;" : "=l"(d) : "l"(a), "l"(b), "l"(c));
    return d;
}

// ---------------- CSR build ----------------
__global__ void k_init() {
    int i = blockIdx.x*blockDim.x + threadIdx.x;
    if (i < NN) { g_deg[i] = 1; g_fill[i] = 0; }   // deg starts at 1: self loop
    if (i < BB*CC) g_pooled[i] = 0.f;
}

__global__ void k_count(const int* __restrict__ dst) {
    int i = blockIdx.x*blockDim.x + threadIdx.x;
    if (i < EE) atomicAdd(&g_deg[dst[i]], 1);
}

// exclusive scan of g_deg[0..NN) -> g_rowptr, single block of 1024 threads
__global__ void k_scan() {
    __shared__ int sh[1024];
    int t = threadIdx.x;
    const int chunk = (NN + 1023) / 1024;
    int beg = t * chunk;
    int end = beg + chunk; if (end > NN) end = NN;
    int sum = 0;
    for (int i = beg; i < end; i++) sum += g_deg[i];
    sh[t] = sum;
    __syncthreads();
    for (int off = 1; off < 1024; off <<= 1) {
        int v = (t >= off) ? sh[t - off] : 0;
        __syncthreads();
        sh[t] += v;
        __syncthreads();
    }
    int run = (t == 0) ? 0 : sh[t - 1];
    for (int i = beg; i < end; i++) { g_rowptr[i] = run; run += g_deg[i]; }
    if (t == 1023) g_rowptr[NN] = sh[1023];
}

__global__ void k_scatter(const int* __restrict__ src, const int* __restrict__ dst) {
    int i = blockIdx.x*blockDim.x + threadIdx.x;
    if (i >= ETOT) return;
    int d, s;
    if (i < EE) { d = dst[i]; s = src[i]; }
    else        { d = i - EE; s = d; }          // self loop
    int pos = g_rowptr[d] + atomicAdd(&g_fill[d], 1);
    g_csr[pos] = s;
}

// ---------------- SGEMM: C[M,N] = A[M,K] @ B[K,N], f32x2 FFMA2 core ----------------
template<int BM,int BN,int BK,int TM,int TN>
__global__ void __launch_bounds__(256)
k_sgemm_t(const float* __restrict__ A, const float* __restrict__ B,
          float* __restrict__ C, int M, int N, int K)
{
    constexpr int THREADS = (BM/TM)*(BN/TN);        // must be 256
    constexpr int AF4 = BM*BK/(4*THREADS);
    constexpr int BF4 = BK*BN/(4*THREADS);
    constexpr int AR  = BK/4;
    constexpr int BR  = BN/4;
    constexpr int GM  = TM/4;
    constexpr int GN  = TN/4;
    constexpr int TN2 = TN/2;

    __shared__ float As[2][BK][BM];
    __shared__ float Bs[2][BK][BN];

    const int bm = blockIdx.y*BM, bn = blockIdx.x*BN;
    const int tid = threadIdx.x;
    const int tx  = tid % (BN/TN);
    const int ty  = tid / (BN/TN);

    float4 ra[AF4], rb[BF4];
    const int nt = K/BK;

    auto ldg = [&](int k0) {
        #pragma unroll
        for (int i = 0; i < AF4; i++) {
            int idx = tid + i*THREADS;
            int r = idx / AR, c4 = (idx % AR)*4;
            int row = bm + r;
            ra[i] = (row < M) ? *(const float4*)(A + (size_t)row*K + k0 + c4)
                              : make_float4(0.f,0.f,0.f,0.f);
        }
        #pragma unroll
        for (int i = 0; i < BF4; i++) {
            int idx = tid + i*THREADS;
            int kk = idx / BR, c4 = (idx % BR)*4;
            rb[i] = *(const float4*)(B + (size_t)(k0+kk)*N + bn + c4);
        }
    };
    auto sts = [&](int buf) {
        #pragma unroll
        for (int i = 0; i < AF4; i++) {
            int idx = tid + i*THREADS;
            int r = idx / AR, c4 = (idx % AR)*4;
            As[buf][c4+0][r] = ra[i].x; As[buf][c4+1][r] = ra[i].y;
            As[buf][c4+2][r] = ra[i].z; As[buf][c4+3][r] = ra[i].w;
        }
        #pragma unroll
        for (int i = 0; i < BF4; i++) {
            int idx = tid + i*THREADS;
            int kk = idx / BR, c4 = (idx % BR)*4;
            *(float4*)&Bs[buf][kk][c4] = rb[i];
        }
    };

    unsigned long long acc[TM][TN2];
    #pragma unroll
    for (int i = 0; i < TM; i++)
        #pragma unroll
        for (int j = 0; j < TN2; j++) acc[i][j] = 0ull;

    ldg(0);
    sts(0);
    __syncthreads();

    for (int t = 0; t < nt; t++) {
        int buf = t & 1;
        if (t + 1 < nt) ldg((t+1)*BK);
        #pragma unroll
        for (int k = 0; k < BK; k++) {
            float a[TM];
            unsigned long long bp[TN2];
            #pragma unroll
            for (int g = 0; g < GM; g++) {
                float4 v = *(const float4*)&As[buf][k][g*(BM/2) + ty*4];
                a[g*4+0]=v.x; a[g*4+1]=v.y; a[g*4+2]=v.z; a[g*4+3]=v.w;
            }
            #pragma unroll
            for (int g = 0; g < GN; g++) {
                float4 v = *(const float4*)&Bs[buf][k][g*(BN/2) + tx*4];
                bp[g*2+0] = pk2(v.x, v.y);
                bp[g*2+1] = pk2(v.z, v.w);
            }
            #pragma unroll
            for (int i = 0; i < TM; i++) {
                unsigned long long ad = pk2(a[i], a[i]);
                #pragma unroll
                for (int j = 0; j < TN2; j++)
                    acc[i][j] = ffma2(ad, bp[j], acc[i][j]);
            }
        }
        if (t + 1 < nt) sts(buf ^ 1);
        __syncthreads();
    }

    #pragma unroll
    for (int g = 0; g < GM; g++) {
        #pragma unroll
        for (int i = 0; i < 4; i++) {
            int row = bm + g*(BM/2) + ty*4 + i;
            if (row >= M) continue;
            #pragma unroll
            for (int h = 0; h < GN; h++) {
                float4 v;
                unpk2(acc[g*4+i][h*2+0], v.x, v.y);
                unpk2(acc[g*4+i][h*2+1], v.z, v.w);
                *(float4*)(C + (size_t)row*N + bn + h*(BN/2) + tx*4) = v;
            }
        }
    }
}

// ---------------- layer-1 attention prep: As1[f,h] = sum_c W1[f,h*C+c]*att_src1[h,c] ----------------
__global__ void k_prep(const float* __restrict__ W,
                       const float* __restrict__ atts, const float* __restrict__ attd) {
    int i = blockIdx.x*blockDim.x + threadIdx.x;
    if (i >= FF*HH) return;
    int f = i / HH, h = i % HH;
    const float* wrow = W + (size_t)f*HC + h*CC;
    float s = 0.f, d = 0.f;
    #pragma unroll 8
    for (int c = 0; c < CC; c++) {
        float w = wrow[c];
        s += w * atts[h*CC + c];
        d += w * attd[h*CC + c];
    }
    g_As1[f*HH + h] = s;
    g_Ad1[f*HH + h] = d;
}

// a_s1[n,h] = x[n,:] . As1[:,h]
__global__ void k_attn_x(const float* __restrict__ x,
                         float* __restrict__ a_s, float* __restrict__ a_d) {
    int i = blockIdx.x*blockDim.x + threadIdx.x;
    if (i >= NN*HH) return;
    int n = i >> 3, h = i & 7;
    const float* xr = x + (size_t)n*FF;
    float s = 0.f, d = 0.f;
    #pragma unroll
    for (int f0 = 0; f0 < FF; f0 += 4) {
        float4 xv = *(const float4*)(xr + f0);
        s += xv.x*g_As1[(f0+0)*HH+h] + xv.y*g_As1[(f0+1)*HH+h]
           + xv.z*g_As1[(f0+2)*HH+h] + xv.w*g_As1[(f0+3)*HH+h];
        d += xv.x*g_Ad1[(f0+0)*HH+h] + xv.y*g_Ad1[(f0+1)*HH+h]
           + xv.z*g_Ad1[(f0+2)*HH+h] + xv.w*g_Ad1[(f0+3)*HH+h];
    }
    a_s[i] = s; a_d[i] = d;
}

// ---------------- attention scores from h (layer 2): warp per node ----------------
__global__ void k_attn(const float* __restrict__ h,
                       const float* __restrict__ asrc,
                       const float* __restrict__ adst,
                       float* __restrict__ a_s, float* __restrict__ a_d,
                       int Hn, int NH) {
    int w = (blockIdx.x * blockDim.x + threadIdx.x) >> 5;
    if (w >= NH) return;
    int lane = threadIdx.x & 31;
    int head = w % Hn;
    const float* hp = h + (size_t)w * CC;
    float v0 = hp[lane], v1 = hp[lane + 32];
    float ps = v0 * __ldg(&asrc[head*CC + lane]) + v1 * __ldg(&asrc[head*CC + lane + 32]);
    float pd = v0 * __ldg(&adst[head*CC + lane]) + v1 * __ldg(&adst[head*CC + lane + 32]);
    #pragma unroll
    for (int o = 16; o; o >>= 1) {
        ps += __shfl_down_sync(0xffffffffu, ps, o);
        pd += __shfl_down_sync(0xffffffffu, pd, o);
    }
    if (lane == 0) { a_s[w] = ps; a_d[w] = pd; }
}

// ---------------- layer-1 GAT aggregation: ONE warp per node, ALL 8 heads ----------------
// smem stages per-edge logits/alphas [edge][head]; gather reads the full
// 512-float h row as 4 independent LDG.128 per lane.
#define MAXDEG 64
__global__ void __launch_bounds__(256) k_agg8(const float* __restrict__ h,
                       const float* __restrict__ a_s,    // [N,8]
                       const float* __restrict__ a_d,    // [N,8]
                       const float* __restrict__ bias,   // [512]
                       float* __restrict__ out) {
    const unsigned FULL = 0xffffffffu;
    __shared__ float s_al[8][MAXDEG*8];
    __shared__ int   s_sr[8][MAXDEG];
    int wb = threadIdx.x >> 5;
    int n  = (blockIdx.x * blockDim.x + threadIdx.x) >> 5;
    if (n >= NN) return;
    int lane = threadIdx.x & 31;
    int beg = g_rowptr[n], end = g_rowptr[n+1];
    int deg = end - beg;
    float* al = s_al[wb];
    int*   sr = s_sr[wb];

    if (deg <= MAXDEG) {
        int hh = lane >> 2, jj = lane & 3;           // 4-way edge parallel per head
        float adn = __ldg(&a_d[n*8 + hh]);

        // phase 1: logits -> smem, per-head running max
        float m = -1e30f;
        for (int e = jj; e < deg; e += 4) {
            int s = g_csr[beg + e];
            if (hh == 0) sr[e] = s;
            float ev = __ldg(&a_s[s*8 + hh]) + adn;
            ev = ev > 0.f ? ev : 0.2f * ev;
            al[e*8 + hh] = ev;
            m = fmaxf(m, ev);
        }
        m = fmaxf(m, __shfl_xor_sync(FULL, m, 1));
        m = fmaxf(m, __shfl_xor_sync(FULL, m, 2));   // lanes of same head agree
        __syncwarp();

        // phase 2a: alpha = exp(e - m[h]); sum per head; scale by 1/sum
        float m_h = __shfl_sync(FULL, m, (lane & 7) * 4);  // m for head lane&7
        float ssum = 0.f;
        for (int i = lane; i < deg*8; i += 32) {     // i&7 == lane&7
            float p = __expf(al[i] - m_h);
            al[i] = p;
            ssum += p;
        }
        ssum += __shfl_xor_sync(FULL, ssum, 8);
        ssum += __shfl_xor_sync(FULL, ssum, 16);
        float inv = 1.f / (ssum + 1e-16f);
        for (int i = lane; i < deg*8; i += 32) al[i] *= inv;
        __syncwarp();

        // phase 2b: gather. lane owns float4 slots {lane, lane+32, lane+64, lane+96}
        int t0 = lane >> 4;                           // 0 or 1
        float4 acc0 = *(const float4*)(bias + 4*(lane));
        float4 acc1 = *(const float4*)(bias + 4*(lane + 32));
        float4 acc2 = *(const float4*)(bias + 4*(lane + 64));
        float4 acc3 = *(const float4*)(bias + 4*(lane + 96));
        for (int e = 0; e < deg; e++) {
            int s = sr[e];
            const float4* hp = (const float4*)(h + (size_t)s * HC);
            float a0 = al[e*8 + t0 + 0];
            float a1 = al[e*8 + t0 + 2];
            float a2 = al[e*8 + t0 + 4];
            float a3 = al[e*8 + t0 + 6];
            float4 v0 = hp[lane], v1 = hp[lane+32], v2 = hp[lane+64], v3 = hp[lane+96];
            acc0.x += a0*v0.x; acc0.y += a0*v0.y; acc0.z += a0*v0.z; acc0.w += a0*v0.w;
            acc1.x += a1*v1.x; acc1.y += a1*v1.y; acc1.z += a1*v1.z; acc1.w += a1*v1.w;
            acc2.x += a2*v2.x; acc2.y += a2*v2.y; acc2.z += a2*v2.z; acc2.w += a2*v2.w;
            acc3.x += a3*v3.x; acc3.y += a3*v3.y; acc3.z += a3*v3.z; acc3.w += a3*v3.w;
        }
        float4* op = (float4*)(out + (size_t)n * HC);
        #define ELU4(v) { v.x = v.x>0.f?v.x:expm1f(v.x); v.y = v.y>0.f?v.y:expm1f(v.y); \
                          v.z = v.z>0.f?v.z:expm1f(v.z); v.w = v.w>0.f?v.w:expm1f(v.w); }
        ELU4(acc0); ELU4(acc1); ELU4(acc2); ELU4(acc3);
        op[lane] = acc0; op[lane+32] = acc1; op[lane+64] = acc2; op[lane+96] = acc3;
    } else {
        // fallback (never hit for this dataset): per-head 3-pass
        for (int head = 0; head < HH; head++) {
            float adn = a_d[n*8 + head];
            float m = -1e30f;
            for (int j = beg + lane; j < end; j += 32) {
                int s = g_csr[j];
                float e = a_s[s*8 + head] + adn;
                e = e > 0.f ? e : 0.2f*e;
                m = fmaxf(m, e);
            }
            #pragma unroll
            for (int o = 16; o; o >>= 1) m = fmaxf(m, __shfl_xor_sync(FULL, m, o));
            float ssum = 0.f;
            for (int j = beg + lane; j < end; j += 32) {
                int s = g_csr[j];
                float e = a_s[s*8 + head] + adn;
                e = e > 0.f ? e : 0.2f*e;
                ssum += __expf(e - m);
            }
            #pragma unroll
            for (int o = 16; o; o >>= 1) ssum += __shfl_xor_sync(FULL, ssum, o);
            float inv = 1.f / (ssum + 1e-16f);
            float acc0 = 0.f, acc1 = 0.f;
            for (int j = beg; j < end; ++j) {
                int s = g_csr[j];
                float e = a_s[s*8 + head] + adn;
                e = e > 0.f ? e : 0.2f*e;
                float alpha = __expf(e - m) * inv;
                const float* hp = h + ((size_t)s*HH + head) * CC;
                acc0 += alpha * hp[lane];
                acc1 += alpha * hp[lane + 32];
            }
            float o0 = acc0 + bias[head*CC + lane];
            float o1 = acc1 + bias[head*CC + lane + 32];
            o0 = o0 > 0.f ? o0 : expm1f(o0);
            o1 = o1 > 0.f ? o1 : expm1f(o1);
            out[((size_t)n*HH + head)*CC + lane]      = o0;
            out[((size_t)n*HH + head)*CC + lane + 32] = o1;
        }
    }
}

// ---------------- GAT aggregation layer 2 (Hn=1): warp per node, 3-pass ----------------
__global__ void k_agg(const float* __restrict__ h,
                      const float* __restrict__ a_s,
                      const float* __restrict__ a_d,
                      const float* __restrict__ bias,
                      float* __restrict__ out,
                      int Hn, int NH) {
    int w = (blockIdx.x * blockDim.x + threadIdx.x) >> 5;
    if (w >= NH) return;
    int lane = threadIdx.x & 31;
    int n = w / Hn, head = w % Hn;
    int beg = g_rowptr[n], end = g_rowptr[n + 1];
    float adn = a_d[w];

    float m = -1e30f;
    for (int j = beg + lane; j < end; j += 32) {
        int s = g_csr[j];
        float e = a_s[s * Hn + head] + adn;
        e = e > 0.f ? e : 0.2f * e;
        m = fmaxf(m, e);
    }
    #pragma unroll
    for (int o = 16; o; o >>= 1) m = fmaxf(m, __shfl_xor_sync(0xffffffffu, m, o));

    float ssum = 0.f;
    for (int j = beg + lane; j < end; j += 32) {
        int s = g_csr[j];
        float e = a_s[s * Hn + head] + adn;
        e = e > 0.f ? e : 0.2f * e;
        ssum += __expf(e - m);
    }
    #pragma unroll
    for (int o = 16; o; o >>= 1) ssum += __shfl_xor_sync(0xffffffffu, ssum, o);
    float inv = 1.f / (ssum + 1e-16f);

    float acc0 = 0.f, acc1 = 0.f;
    for (int j = beg; j < end; ++j) {
        int s = g_csr[j];
        float e = a_s[s * Hn + head] + adn;
        e = e > 0.f ? e : 0.2f * e;
        float alpha = __expf(e - m) * inv;
        const float* hp = h + ((size_t)s * Hn + head) * CC;
        acc0 += alpha * hp[lane];
        acc1 += alpha * hp[lane + 32];
    }
    float o0 = acc0 + bias[head*CC + lane];
    float o1 = acc1 + bias[head*CC + lane + 32];
    o0 = o0 > 0.f ? o0 : expm1f(o0);
    o1 = o1 > 0.f ? o1 : expm1f(o1);
    out[(size_t)w * CC + lane]      = o0;
    out[(size_t)w * CC + lane + 32] = o1;
}

// ---------------- global add pool (batch is sorted) ----------------
__global__ void k_pool(const int* __restrict__ batch) {
    int c = threadIdx.x;             // 64 channels
    int n0 = blockIdx.x * 128;
    int n1 = n0 + 128; if (n1 > NN) n1 = NN;
    if (n0 >= NN) return;
    float acc = 0.f;
    int cur = batch[n0];
    for (int i = n0; i < n1; i++) {
        int b = batch[i];
        if (b != cur) { atomicAdd(&g_pooled[cur*CC + c], acc); acc = 0.f; cur = b; }
        acc += g_out2[(size_t)i * CC + c];
    }
    atomicAdd(&g_pooled[cur*CC + c], acc);
}

// ---------------- head MLP + log_softmax, one block of 64 per graph ----------------
__global__ void k_head(const float* __restrict__ w1, const float* __restrict__ b1v,
                       const float* __restrict__ w2, const float* __restrict__ b2v,
                       float* __restrict__ out) {
    __shared__ float p[64], zs[64], lg[KK];
    int b = blockIdx.x, t = threadIdx.x;
    p[t] = g_pooled[b*CC + t];
    __syncthreads();
    float z = b1v[t];
    #pragma unroll 16
    for (int k = 0; k < 64; k++) z += p[k] * w1[k*64 + t];
    z = z > 0.f ? z : expm1f(z);
    zs[t] = z;
    __syncthreads();
    if (t < KK) {
        float l = b2v[t];
        #pragma unroll 16
        for (int k = 0; k < 64; k++) l += zs[k] * w2[k*KK + t];
        lg[t] = l;
    }
    __syncthreads();
    if (t < KK) {
        float m = -1e30f;
        #pragma unroll
        for (int k = 0; k < KK; k++) m = fmaxf(m, lg[k]);
        float s = 0.f;
        #pragma unroll
        for (int k = 0; k < KK; k++) s += expf(lg[k] - m);
        out[b*KK + t] = lg[t] - m - logf(s);
    }
}

// ---------------- launch ----------------
extern "C" void kernel_launch(void* const* d_in, const int* in_sizes, int n_in,
                              void* d_out, int out_size) {
    const float* x        = (const float*)d_in[0];
    const int*   ei       = (const int*)  d_in[1];
    const int*   batch    = (const int*)  d_in[2];
    const float* W1       = (const float*)d_in[3];
    const float* att_src1 = (const float*)d_in[4];
    const float* att_dst1 = (const float*)d_in[5];
    const float* b1       = (const float*)d_in[6];
    const float* W2       = (const float*)d_in[7];
    const float* att_src2 = (const float*)d_in[8];
    const float* att_dst2 = (const float*)d_in[9];
    const float* b2       = (const float*)d_in[10];
    const float* l1w      = (const float*)d_in[11];
    const float* l1b      = (const float*)d_in[12];
    const float* l2w      = (const float*)d_in[13];
    const float* l2b      = (const float*)d_in[14];
    float* out = (float*)d_out;

    const int* src = ei;
    const int* dst = ei + EE;

    void *p_h1, *p_out1, *p_h2, *p_out2, *p_as1, *p_ad1, *p_as2, *p_ad2;
    cudaGetSymbolAddress(&p_h1,  g_h1);
    cudaGetSymbolAddress(&p_out1, g_out1);
    cudaGetSymbolAddress(&p_h2,  g_h2);
    cudaGetSymbolAddress(&p_out2, g_out2);
    cudaGetSymbolAddress(&p_as1, g_as1);
    cudaGetSymbolAddress(&p_ad1, g_ad1);
    cudaGetSymbolAddress(&p_as2, g_as2);
    cudaGetSymbolAddress(&p_ad2, g_ad2);
    float* h1   = (float*)p_h1;
    float* out1 = (float*)p_out1;
    float* h2   = (float*)p_h2;
    float* out2 = (float*)p_out2;
    float* as1  = (float*)p_as1;
    float* ad1  = (float*)p_ad1;
    float* as2  = (float*)p_as2;
    float* ad2  = (float*)p_ad2;

    // CSR prefix work
    k_init<<<(NN + 255)/256, 256>>>();
    k_count<<<(EE + 255)/256, 256>>>(dst);
    k_scan<<<1, 1024>>>();

    // GEMM1 placed in the ncu-captured launch slot (no dependency on CSR)
    k_sgemm_t<128,128,16,8,8><<<dim3(HC/128, (NN + 127)/128), 256>>>(x, W1, h1, NN, HC, FF);

    // layer-1 attention scores straight from x
    k_prep<<<(FF*HH + 255)/256, 256>>>(W1, att_src1, att_dst1);
    k_attn_x<<<(NN*HH + 255)/256, 256>>>(x, as1, ad1);

    // finish CSR
    k_scatter<<<(ETOT + 255)/256, 256>>>(src, dst);

    // Layer 1 aggregation: one warp per node, all heads
    k_agg8<<<(NN + 7)/8, 256>>>(h1, as1, ad1, b1, out1);

    // Layer 2: h2 = out1 @ W2  [50000,512]@[512,64]
    k_sgemm_t<128,64,16,8,4><<<dim3(CC/64, (NN + 127)/128), 256>>>(out1, W2, h2, NN, CC, HC);
    k_attn<<<(NN + 7)/8, 256>>>(h2, att_src2, att_dst2, as2, ad2, 1, NN);
    k_agg <<<(NN + 7)/8, 256>>>(h2, as2, ad2, b2, out2, 1, NN);

    // Pool + head
    k_pool<<<(NN + 127)/128, 64>>>(batch);
    k_head<<<BB, 64>>>(l1w, l1b, l2w, l2b, out);
}

// round 13
// speedup vs baseline: 1.2705x; 1.2705x over previous
#include <cuda_runtime.h>
#include <math.h>

#define NN 50000
#define EE 400000
#define FF 128
#define HH 8
#define CC 64
#define BB 64
#define KK 10
#define HC (HH*CC)     /* 512 */
#define ETOT (EE+NN)   /* 450000 edges incl. self loops */

// ---------------- scratch (device globals; no allocation allowed) ----------------
__device__ __align__(16) float g_h1[(size_t)NN*HC];    // x@W1
__device__ __align__(16) float g_out1[(size_t)NN*HC];  // elu(gat1)
__device__ __align__(16) float g_h2[(size_t)NN*CC];    // out1@W2
__device__ __align__(16) float g_out2[(size_t)NN*CC];  // elu(gat2)
__device__ __align__(16) float g_as1[NN*HH];
__device__ __align__(16) float g_ad1[NN*HH];
__device__ __align__(16) float g_as2[NN];
__device__ __align__(16) float g_ad2[NN];
__device__ __align__(16) float g_pooled[BB*CC];
__device__ __align__(16) float g_As1[FF*HH];   // W1 contracted with att_src1
__device__ __align__(16) float g_Ad1[FF*HH];   // W1 contracted with att_dst1
__device__ int g_deg[NN];
__device__ int g_rowptr[NN+1];
__device__ int g_fill[NN];
__device__ int g_csr[ETOT];

// ---------------- f32x2 packed helpers (Blackwell FFMA2) ----------------
__device__ __forceinline__ unsigned long long pk2(float lo, float hi) {
    unsigned long long r;
    asm("mov.b64 %0, {%1, %2};" : "=l"(r) : "r"(__float_as_uint(lo)), "r"(__float_as_uint(hi)));
    return r;
}
__device__ __forceinline__ void unpk2(unsigned long long v, float& lo, float& hi) {
    unsigned int a, b;
    asm("mov.b64 {%0, %1}, %2;" : "=r"(a), "=r"(b) : "l"(v));
    lo = __uint_as_float(a); hi = __uint_as_float(b);
}
__device__ __forceinline__ unsigned long long ffma2(unsigned long long a,
                                                    unsigned long long b,
                                                    unsigned long long c) {
    unsigned long long d;
    asm("fma.rn.f32x2 %0, %1, %2, %3;" : "=l"(d) : "l"(a), "l"(b), "l"(c));
    return d;
}

// ---------------- CSR build ----------------
__global__ void k_init() {
    int i = blockIdx.x*blockDim.x + threadIdx.x;
    if (i < NN) { g_deg[i] = 1; g_fill[i] = 0; }   // deg starts at 1: self loop
    if (i < BB*CC) g_pooled[i] = 0.f;
}

__global__ void k_count(const int* __restrict__ dst) {
    int i = blockIdx.x*blockDim.x + threadIdx.x;
    if (i < EE) atomicAdd(&g_deg[dst[i]], 1);
}

// exclusive scan of g_deg[0..NN) -> g_rowptr, single block of 1024 threads
__global__ void k_scan() {
    __shared__ int sh[1024];
    int t = threadIdx.x;
    const int chunk = (NN + 1023) / 1024;
    int beg = t * chunk;
    int end = beg + chunk; if (end > NN) end = NN;
    int sum = 0;
    for (int i = beg; i < end; i++) sum += g_deg[i];
    sh[t] = sum;
    __syncthreads();
    for (int off = 1; off < 1024; off <<= 1) {
        int v = (t >= off) ? sh[t - off] : 0;
        __syncthreads();
        sh[t] += v;
        __syncthreads();
    }
    int run = (t == 0) ? 0 : sh[t - 1];
    for (int i = beg; i < end; i++) { g_rowptr[i] = run; run += g_deg[i]; }
    if (t == 1023) g_rowptr[NN] = sh[1023];
}

__global__ void k_scatter(const int* __restrict__ src, const int* __restrict__ dst) {
    int i = blockIdx.x*blockDim.x + threadIdx.x;
    if (i >= ETOT) return;
    int d, s;
    if (i < EE) { d = dst[i]; s = src[i]; }
    else        { d = i - EE; s = d; }          // self loop
    int pos = g_rowptr[d] + atomicAdd(&g_fill[d], 1);
    g_csr[pos] = s;
}

// ---------------- SGEMM: C[M,N] = A[M,K] @ B[K,N], f32x2 FFMA2 core ----------------
// __launch_bounds__(256, 2): cap regs at 128 so TWO CTAs fit per SM
// (R11 ncu: 140 regs -> 1 CTA/SM -> occ 12.4%, issue 39.5%).
template<int BM,int BN,int BK,int TM,int TN>
__global__ void __launch_bounds__(256, 2)
k_sgemm_t(const float* __restrict__ A, const float* __restrict__ B,
          float* __restrict__ C, int M, int N, int K)
{
    constexpr int THREADS = (BM/TM)*(BN/TN);        // must be 256
    constexpr int AF4 = BM*BK/(4*THREADS);
    constexpr int BF4 = BK*BN/(4*THREADS);
    constexpr int AR  = BK/4;
    constexpr int BR  = BN/4;
    constexpr int GM  = TM/4;
    constexpr int GN  = TN/4;
    constexpr int TN2 = TN/2;

    __shared__ float As[2][BK][BM];
    __shared__ float Bs[2][BK][BN];

    const int bm = blockIdx.y*BM, bn = blockIdx.x*BN;
    const int tid = threadIdx.x;
    const int tx  = tid % (BN/TN);
    const int ty  = tid / (BN/TN);

    float4 ra[AF4], rb[BF4];
    const int nt = K/BK;

    auto ldg = [&](int k0) {
        #pragma unroll
        for (int i = 0; i < AF4; i++) {
            int idx = tid + i*THREADS;
            int r = idx / AR, c4 = (idx % AR)*4;
            int row = bm + r;
            ra[i] = (row < M) ? *(const float4*)(A + (size_t)row*K + k0 + c4)
                              : make_float4(0.f,0.f,0.f,0.f);
        }
        #pragma unroll
        for (int i = 0; i < BF4; i++) {
            int idx = tid + i*THREADS;
            int kk = idx / BR, c4 = (idx % BR)*4;
            rb[i] = *(const float4*)(B + (size_t)(k0+kk)*N + bn + c4);
        }
    };
    auto sts = [&](int buf) {
        #pragma unroll
        for (int i = 0; i < AF4; i++) {
            int idx = tid + i*THREADS;
            int r = idx / AR, c4 = (idx % AR)*4;
            As[buf][c4+0][r] = ra[i].x; As[buf][c4+1][r] = ra[i].y;
            As[buf][c4+2][r] = ra[i].z; As[buf][c4+3][r] = ra[i].w;
        }
        #pragma unroll
        for (int i = 0; i < BF4; i++) {
            int idx = tid + i*THREADS;
            int kk = idx / BR, c4 = (idx % BR)*4;
            *(float4*)&Bs[buf][kk][c4] = rb[i];
        }
    };

    unsigned long long acc[TM][TN2];
    #pragma unroll
    for (int i = 0; i < TM; i++)
        #pragma unroll
        for (int j = 0; j < TN2; j++) acc[i][j] = 0ull;

    ldg(0);
    sts(0);
    __syncthreads();

    for (int t = 0; t < nt; t++) {
        int buf = t & 1;
        if (t + 1 < nt) ldg((t+1)*BK);
        #pragma unroll
        for (int k = 0; k < BK; k++) {
            float a[TM];
            unsigned long long bp[TN2];
            #pragma unroll
            for (int g = 0; g < GM; g++) {
                float4 v = *(const float4*)&As[buf][k][g*(BM/2) + ty*4];
                a[g*4+0]=v.x; a[g*4+1]=v.y; a[g*4+2]=v.z; a[g*4+3]=v.w;
            }
            #pragma unroll
            for (int g = 0; g < GN; g++) {
                float4 v = *(const float4*)&Bs[buf][k][g*(BN/2) + tx*4];
                bp[g*2+0] = pk2(v.x, v.y);
                bp[g*2+1] = pk2(v.z, v.w);
            }
            #pragma unroll
            for (int i = 0; i < TM; i++) {
                unsigned long long ad = pk2(a[i], a[i]);
                #pragma unroll
                for (int j = 0; j < TN2; j++)
                    acc[i][j] = ffma2(ad, bp[j], acc[i][j]);
            }
        }
        if (t + 1 < nt) sts(buf ^ 1);
        __syncthreads();
    }

    #pragma unroll
    for (int g = 0; g < GM; g++) {
        #pragma unroll
        for (int i = 0; i < 4; i++) {
            int row = bm + g*(BM/2) + ty*4 + i;
            if (row >= M) continue;
            #pragma unroll
            for (int h = 0; h < GN; h++) {
                float4 v;
                unpk2(acc[g*4+i][h*2+0], v.x, v.y);
                unpk2(acc[g*4+i][h*2+1], v.z, v.w);
                *(float4*)(C + (size_t)row*N + bn + h*(BN/2) + tx*4) = v;
            }
        }
    }
}

// ---------------- layer-1 attention prep: As1[f,h] = sum_c W1[f,h*C+c]*att_src1[h,c] ----------------
__global__ void k_prep(const float* __restrict__ W,
                       const float* __restrict__ atts, const float* __restrict__ attd) {
    int i = blockIdx.x*blockDim.x + threadIdx.x;
    if (i >= FF*HH) return;
    int f = i / HH, h = i % HH;
    const float* wrow = W + (size_t)f*HC + h*CC;
    float s = 0.f, d = 0.f;
    #pragma unroll 8
    for (int c = 0; c < CC; c++) {
        float w = wrow[c];
        s += w * atts[h*CC + c];
        d += w * attd[h*CC + c];
    }
    g_As1[f*HH + h] = s;
    g_Ad1[f*HH + h] = d;
}

// a_s1[n,h] = x[n,:] . As1[:,h]
__global__ void k_attn_x(const float* __restrict__ x,
                         float* __restrict__ a_s, float* __restrict__ a_d) {
    int i = blockIdx.x*blockDim.x + threadIdx.x;
    if (i >= NN*HH) return;
    int n = i >> 3, h = i & 7;
    const float* xr = x + (size_t)n*FF;
    float s = 0.f, d = 0.f;
    #pragma unroll
    for (int f0 = 0; f0 < FF; f0 += 4) {
        float4 xv = *(const float4*)(xr + f0);
        s += xv.x*g_As1[(f0+0)*HH+h] + xv.y*g_As1[(f0+1)*HH+h]
           + xv.z*g_As1[(f0+2)*HH+h] + xv.w*g_As1[(f0+3)*HH+h];
        d += xv.x*g_Ad1[(f0+0)*HH+h] + xv.y*g_Ad1[(f0+1)*HH+h]
           + xv.z*g_Ad1[(f0+2)*HH+h] + xv.w*g_Ad1[(f0+3)*HH+h];
    }
    a_s[i] = s; a_d[i] = d;
}

// ---------------- attention scores from h (layer 2): warp per node ----------------
__global__ void k_attn(const float* __restrict__ h,
                       const float* __restrict__ asrc,
                       const float* __restrict__ adst,
                       float* __restrict__ a_s, float* __restrict__ a_d,
                       int Hn, int NH) {
    int w = (blockIdx.x * blockDim.x + threadIdx.x) >> 5;
    if (w >= NH) return;
    int lane = threadIdx.x & 31;
    int head = w % Hn;
    const float* hp = h + (size_t)w * CC;
    float v0 = hp[lane], v1 = hp[lane + 32];
    float ps = v0 * __ldg(&asrc[head*CC + lane]) + v1 * __ldg(&asrc[head*CC + lane + 32]);
    float pd = v0 * __ldg(&adst[head*CC + lane]) + v1 * __ldg(&adst[head*CC + lane + 32]);
    #pragma unroll
    for (int o = 16; o; o >>= 1) {
        ps += __shfl_down_sync(0xffffffffu, ps, o);
        pd += __shfl_down_sync(0xffffffffu, pd, o);
    }
    if (lane == 0) { a_s[w] = ps; a_d[w] = pd; }
}

// ---------------- GAT aggregation: warp per (node, head), segment softmax + gather ----------------
__global__ void k_agg(const float* __restrict__ h,
                      const float* __restrict__ a_s,
                      const float* __restrict__ a_d,
                      const float* __restrict__ bias,
                      float* __restrict__ out,
                      int Hn, int NH) {
    int w = (blockIdx.x * blockDim.x + threadIdx.x) >> 5;
    if (w >= NH) return;
    int lane = threadIdx.x & 31;
    int n = w / Hn, head = w % Hn;
    int beg = g_rowptr[n], end = g_rowptr[n + 1];
    float adn = a_d[w];

    // pass 1: segment max (lane-parallel over edges)
    float m = -1e30f;
    for (int j = beg + lane; j < end; j += 32) {
        int s = g_csr[j];
        float e = a_s[s * Hn + head] + adn;
        e = e > 0.f ? e : 0.2f * e;
        m = fmaxf(m, e);
    }
    #pragma unroll
    for (int o = 16; o; o >>= 1) m = fmaxf(m, __shfl_xor_sync(0xffffffffu, m, o));

    // pass 2: denom
    float ssum = 0.f;
    for (int j = beg + lane; j < end; j += 32) {
        int s = g_csr[j];
        float e = a_s[s * Hn + head] + adn;
        e = e > 0.f ? e : 0.2f * e;
        ssum += __expf(e - m);
    }
    #pragma unroll
    for (int o = 16; o; o >>= 1) ssum += __shfl_xor_sync(0xffffffffu, ssum, o);
    float inv = 1.f / (ssum + 1e-16f);

    // pass 3: weighted gather (all lanes walk edges; lane = channel)
    float acc0 = 0.f, acc1 = 0.f;
    for (int j = beg; j < end; ++j) {
        int s = g_csr[j];
        float e = a_s[s * Hn + head] + adn;
        e = e > 0.f ? e : 0.2f * e;
        float alpha = __expf(e - m) * inv;
        const float* hp = h + ((size_t)s * Hn + head) * CC;
        acc0 += alpha * hp[lane];
        acc1 += alpha * hp[lane + 32];
    }
    float o0 = acc0 + bias[head*CC + lane];
    float o1 = acc1 + bias[head*CC + lane + 32];
    o0 = o0 > 0.f ? o0 : expm1f(o0);   // fused ELU
    o1 = o1 > 0.f ? o1 : expm1f(o1);
    out[(size_t)w * CC + lane]      = o0;
    out[(size_t)w * CC + lane + 32] = o1;
}

// ---------------- global add pool (batch is sorted) ----------------
__global__ void k_pool(const int* __restrict__ batch) {
    int c = threadIdx.x;             // 64 channels
    int n0 = blockIdx.x * 128;
    int n1 = n0 + 128; if (n1 > NN) n1 = NN;
    if (n0 >= NN) return;
    float acc = 0.f;
    int cur = batch[n0];
    for (int i = n0; i < n1; i++) {
        int b = batch[i];
        if (b != cur) { atomicAdd(&g_pooled[cur*CC + c], acc); acc = 0.f; cur = b; }
        acc += g_out2[(size_t)i * CC + c];
    }
    atomicAdd(&g_pooled[cur*CC + c], acc);
}

// ---------------- head MLP + log_softmax, one block of 64 per graph ----------------
__global__ void k_head(const float* __restrict__ w1, const float* __restrict__ b1v,
                       const float* __restrict__ w2, const float* __restrict__ b2v,
                       float* __restrict__ out) {
    __shared__ float p[64], zs[64], lg[KK];
    int b = blockIdx.x, t = threadIdx.x;
    p[t] = g_pooled[b*CC + t];
    __syncthreads();
    float z = b1v[t];
    #pragma unroll 16
    for (int k = 0; k < 64; k++) z += p[k] * w1[k*64 + t];
    z = z > 0.f ? z : expm1f(z);
    zs[t] = z;
    __syncthreads();
    if (t < KK) {
        float l = b2v[t];
        #pragma unroll 16
        for (int k = 0; k < 64; k++) l += zs[k] * w2[k*KK + t];
        lg[t] = l;
    }
    __syncthreads();
    if (t < KK) {
        float m = -1e30f;
        #pragma unroll
        for (int k = 0; k < KK; k++) m = fmaxf(m, lg[k]);
        float s = 0.f;
        #pragma unroll
        for (int k = 0; k < KK; k++) s += expf(lg[k] - m);
        out[b*KK + t] = lg[t] - m - logf(s);
    }
}

// ---------------- launch ----------------
extern "C" void kernel_launch(void* const* d_in, const int* in_sizes, int n_in,
                              void* d_out, int out_size) {
    const float* x        = (const float*)d_in[0];
    const int*   ei       = (const int*)  d_in[1];
    const int*   batch    = (const int*)  d_in[2];
    const float* W1       = (const float*)d_in[3];
    const float* att_src1 = (const float*)d_in[4];
    const float* att_dst1 = (const float*)d_in[5];
    const float* b1       = (const float*)d_in[6];
    const float* W2       = (const float*)d_in[7];
    const float* att_src2 = (const float*)d_in[8];
    const float* att_dst2 = (const float*)d_in[9];
    const float* b2       = (const float*)d_in[10];
    const float* l1w      = (const float*)d_in[11];
    const float* l1b      = (const float*)d_in[12];
    const float* l2w      = (const float*)d_in[13];
    const float* l2b      = (const float*)d_in[14];
    float* out = (float*)d_out;

    const int* src = ei;
    const int* dst = ei + EE;

    void *p_h1, *p_out1, *p_h2, *p_out2, *p_as1, *p_ad1, *p_as2, *p_ad2;
    cudaGetSymbolAddress(&p_h1,  g_h1);
    cudaGetSymbolAddress(&p_out1, g_out1);
    cudaGetSymbolAddress(&p_h2,  g_h2);
    cudaGetSymbolAddress(&p_out2, g_out2);
    cudaGetSymbolAddress(&p_as1, g_as1);
    cudaGetSymbolAddress(&p_ad1, g_ad1);
    cudaGetSymbolAddress(&p_as2, g_as2);
    cudaGetSymbolAddress(&p_ad2, g_ad2);
    float* h1   = (float*)p_h1;
    float* out1 = (float*)p_out1;
    float* h2   = (float*)p_h2;
    float* out2 = (float*)p_out2;
    float* as1  = (float*)p_as1;
    float* ad1  = (float*)p_ad1;
    float* as2  = (float*)p_as2;
    float* ad2  = (float*)p_ad2;

    // CSR prefix work
    k_init<<<(NN + 255)/256, 256>>>();
    k_count<<<(EE + 255)/256, 256>>>(dst);
    k_scan<<<1, 1024>>>();

    // GEMM1 in the ncu-captured launch slot (no dependency on CSR)
    k_sgemm_t<128,128,16,8,8><<<dim3(HC/128, (NN + 127)/128), 256>>>(x, W1, h1, NN, HC, FF);

    // layer-1 attention scores straight from x
    k_prep<<<(FF*HH + 255)/256, 256>>>(W1, att_src1, att_dst1);
    k_attn_x<<<(NN*HH + 255)/256, 256>>>(x, as1, ad1);

    // finish CSR
    k_scatter<<<(ETOT + 255)/256, 256>>>(src, dst);

    // Layer 1 aggregation (verified 3-pass warp-per-(node,head))
    k_agg <<<(NN*HH + 7)/8, 256>>>(h1, as1, ad1, b1, out1, HH, NN*HH);

    // Layer 2: h2 = out1 @ W2  [50000,512]@[512,64]
    k_sgemm_t<128,64,16,8,4><<<dim3(CC/64, (NN + 127)/128), 256>>>(out1, W2, h2, NN, CC, HC);
    k_attn<<<(NN + 7)/8, 256>>>(h2, att_src2, att_dst2, as2, ad2, 1, NN);
    k_agg <<<(NN + 7)/8, 256>>>(h2, as2, ad2, b2, out2, 1, NN);

    // Pool + head
    k_pool<<<(NN + 127)/128, 64>>>(batch);
    k_head<<<BB, 64>>>(l1w, l1b, l2w, l2b, out);
}

// round 14
// speedup vs baseline: 1.3345x; 1.0504x over previous
#include <cuda_runtime.h>
#include <math.h>

#define NN 50000
#define EE 400000
#define FF 128
#define HH 8
#define CC 64
#define BB 64
#define KK 10
#define HC (HH*CC)     /* 512 */
#define ETOT (EE+NN)   /* 450000 edges incl. self loops */

// ---------------- scratch (device globals; no allocation allowed) ----------------
__device__ __align__(16) float g_h1[(size_t)NN*HC];    // x@W1
__device__ __align__(16) float g_out1[(size_t)NN*HC];  // elu(gat1)
__device__ __align__(16) float g_h2[(size_t)NN*CC];    // out1@W2
__device__ __align__(16) float g_out2[(size_t)NN*CC];  // elu(gat2)
__device__ __align__(16) float g_as1[NN*HH];
__device__ __align__(16) float g_ad1[NN*HH];
__device__ __align__(16) float g_as2[NN];
__device__ __align__(16) float g_ad2[NN];
__device__ __align__(16) float g_pooled[BB*CC];
__device__ __align__(16) float g_As1[FF*HH];   // W1 contracted with att_src1
__device__ __align__(16) float g_Ad1[FF*HH];   // W1 contracted with att_dst1
__device__ int g_deg[NN];
__device__ int g_rowptr[NN+1];
__device__ int g_fill[NN];
__device__ int g_csr[ETOT];

// ---------------- f32x2 packed helpers (Blackwell FFMA2) ----------------
__device__ __forceinline__ unsigned long long pk2(float lo, float hi) {
    unsigned long long r;
    asm("mov.b64 %0, {%1, %2};" : "=l"(r) : "r"(__float_as_uint(lo)), "r"(__float_as_uint(hi)));
    return r;
}
__device__ __forceinline__ void unpk2(unsigned long long v, float& lo, float& hi) {
    unsigned int a, b;
    asm("mov.b64 {%0, %1}, %2;" : "=r"(a), "=r"(b) : "l"(v));
    lo = __uint_as_float(a); hi = __uint_as_float(b);
}
__device__ __forceinline__ unsigned long long ffma2(unsigned long long a,
                                                    unsigned long long b,
                                                    unsigned long long c) {
    unsigned long long d;
    asm("fma.rn.f32x2 %0, %1, %2, %3;" : "=l"(d) : "l"(a), "l"(b), "l"(c));
    return d;
}

// ---------------- CSR build ----------------
__global__ void k_init() {
    int i = blockIdx.x*blockDim.x + threadIdx.x;
    if (i < NN) { g_deg[i] = 1; g_fill[i] = 0; }   // deg starts at 1: self loop
    if (i < BB*CC) g_pooled[i] = 0.f;
}

__global__ void k_count(const int* __restrict__ dst) {
    int i = blockIdx.x*blockDim.x + threadIdx.x;
    if (i < EE) atomicAdd(&g_deg[dst[i]], 1);
}

// exclusive scan of g_deg[0..NN) -> g_rowptr, single block of 1024 threads
__global__ void k_scan() {
    __shared__ int sh[1024];
    int t = threadIdx.x;
    const int chunk = (NN + 1023) / 1024;
    int beg = t * chunk;
    int end = beg + chunk; if (end > NN) end = NN;
    int sum = 0;
    for (int i = beg; i < end; i++) sum += g_deg[i];
    sh[t] = sum;
    __syncthreads();
    for (int off = 1; off < 1024; off <<= 1) {
        int v = (t >= off) ? sh[t - off] : 0;
        __syncthreads();
        sh[t] += v;
        __syncthreads();
    }
    int run = (t == 0) ? 0 : sh[t - 1];
    for (int i = beg; i < end; i++) { g_rowptr[i] = run; run += g_deg[i]; }
    if (t == 1023) g_rowptr[NN] = sh[1023];
}

__global__ void k_scatter(const int* __restrict__ src, const int* __restrict__ dst) {
    int i = blockIdx.x*blockDim.x + threadIdx.x;
    if (i >= ETOT) return;
    int d, s;
    if (i < EE) { d = dst[i]; s = src[i]; }
    else        { d = i - EE; s = d; }          // self loop
    int pos = g_rowptr[d] + atomicAdd(&g_fill[d], 1);
    g_csr[pos] = s;
}

// ---------------- SGEMM: C[M,N] = A[M,K] @ B[K,N], f32x2 FFMA2 core ----------------
// MINB CTAs/SM minimum (register cap). BM=128/BN=64/TM=8/TN=4 @ MINB=3:
// acc is 32 regs -> ~75 live -> fits the 85-reg budget, 24 warps/SM.
template<int BM,int BN,int BK,int TM,int TN,int MINB>
__global__ void __launch_bounds__(256, MINB)
k_sgemm_t(const float* __restrict__ A, const float* __restrict__ B,
          float* __restrict__ C, int M, int N, int K)
{
    constexpr int THREADS = (BM/TM)*(BN/TN);        // must be 256
    constexpr int AF4 = BM*BK/(4*THREADS);
    constexpr int BF4 = BK*BN/(4*THREADS);
    constexpr int AR  = BK/4;
    constexpr int BR  = BN/4;
    constexpr int GM  = TM/4;
    constexpr int GN  = TN/4;
    constexpr int TN2 = TN/2;

    __shared__ float As[2][BK][BM];
    __shared__ float Bs[2][BK][BN];

    const int bm = blockIdx.y*BM, bn = blockIdx.x*BN;
    const int tid = threadIdx.x;
    const int tx  = tid % (BN/TN);
    const int ty  = tid / (BN/TN);

    float4 ra[AF4], rb[BF4];
    const int nt = K/BK;

    auto ldg = [&](int k0) {
        #pragma unroll
        for (int i = 0; i < AF4; i++) {
            int idx = tid + i*THREADS;
            int r = idx / AR, c4 = (idx % AR)*4;
            int row = bm + r;
            ra[i] = (row < M) ? *(const float4*)(A + (size_t)row*K + k0 + c4)
                              : make_float4(0.f,0.f,0.f,0.f);
        }
        #pragma unroll
        for (int i = 0; i < BF4; i++) {
            int idx = tid + i*THREADS;
            int kk = idx / BR, c4 = (idx % BR)*4;
            rb[i] = *(const float4*)(B + (size_t)(k0+kk)*N + bn + c4);
        }
    };
    auto sts = [&](int buf) {
        #pragma unroll
        for (int i = 0; i < AF4; i++) {
            int idx = tid + i*THREADS;
            int r = idx / AR, c4 = (idx % AR)*4;
            As[buf][c4+0][r] = ra[i].x; As[buf][c4+1][r] = ra[i].y;
            As[buf][c4+2][r] = ra[i].z; As[buf][c4+3][r] = ra[i].w;
        }
        #pragma unroll
        for (int i = 0; i < BF4; i++) {
            int idx = tid + i*THREADS;
            int kk = idx / BR, c4 = (idx % BR)*4;
            *(float4*)&Bs[buf][kk][c4] = rb[i];
        }
    };

    unsigned long long acc[TM][TN2];
    #pragma unroll
    for (int i = 0; i < TM; i++)
        #pragma unroll
        for (int j = 0; j < TN2; j++) acc[i][j] = 0ull;

    ldg(0);
    sts(0);
    __syncthreads();

    for (int t = 0; t < nt; t++) {
        int buf = t & 1;
        if (t + 1 < nt) ldg((t+1)*BK);
        #pragma unroll
        for (int k = 0; k < BK; k++) {
            float a[TM];
            unsigned long long bp[TN2];
            #pragma unroll
            for (int g = 0; g < GM; g++) {
                float4 v = *(const float4*)&As[buf][k][g*(BM/2) + ty*4];
                a[g*4+0]=v.x; a[g*4+1]=v.y; a[g*4+2]=v.z; a[g*4+3]=v.w;
            }
            #pragma unroll
            for (int g = 0; g < GN; g++) {
                float4 v = *(const float4*)&Bs[buf][k][g*(BN/2) + tx*4];
                bp[g*2+0] = pk2(v.x, v.y);
                bp[g*2+1] = pk2(v.z, v.w);
            }
            #pragma unroll
            for (int i = 0; i < TM; i++) {
                unsigned long long ad = pk2(a[i], a[i]);
                #pragma unroll
                for (int j = 0; j < TN2; j++)
                    acc[i][j] = ffma2(ad, bp[j], acc[i][j]);
            }
        }
        if (t + 1 < nt) sts(buf ^ 1);
        __syncthreads();
    }

    #pragma unroll
    for (int g = 0; g < GM; g++) {
        #pragma unroll
        for (int i = 0; i < 4; i++) {
            int row = bm + g*(BM/2) + ty*4 + i;
            if (row >= M) continue;
            #pragma unroll
            for (int h = 0; h < GN; h++) {
                float4 v;
                unpk2(acc[g*4+i][h*2+0], v.x, v.y);
                unpk2(acc[g*4+i][h*2+1], v.z, v.w);
                *(float4*)(C + (size_t)row*N + bn + h*(BN/2) + tx*4) = v;
            }
        }
    }
}

// ---------------- layer-1 attention prep: As1[f,h] = sum_c W1[f,h*C+c]*att_src1[h,c] ----------------
__global__ void k_prep(const float* __restrict__ W,
                       const float* __restrict__ atts, const float* __restrict__ attd) {
    int i = blockIdx.x*blockDim.x + threadIdx.x;
    if (i >= FF*HH) return;
    int f = i / HH, h = i % HH;
    const float* wrow = W + (size_t)f*HC + h*CC;
    float s = 0.f, d = 0.f;
    #pragma unroll 8
    for (int c = 0; c < CC; c++) {
        float w = wrow[c];
        s += w * atts[h*CC + c];
        d += w * attd[h*CC + c];
    }
    g_As1[f*HH + h] = s;
    g_Ad1[f*HH + h] = d;
}

// a_s1[n,h] = x[n,:] . As1[:,h]
__global__ void k_attn_x(const float* __restrict__ x,
                         float* __restrict__ a_s, float* __restrict__ a_d) {
    int i = blockIdx.x*blockDim.x + threadIdx.x;
    if (i >= NN*HH) return;
    int n = i >> 3, h = i & 7;
    const float* xr = x + (size_t)n*FF;
    float s = 0.f, d = 0.f;
    #pragma unroll
    for (int f0 = 0; f0 < FF; f0 += 4) {
        float4 xv = *(const float4*)(xr + f0);
        s += xv.x*g_As1[(f0+0)*HH+h] + xv.y*g_As1[(f0+1)*HH+h]
           + xv.z*g_As1[(f0+2)*HH+h] + xv.w*g_As1[(f0+3)*HH+h];
        d += xv.x*g_Ad1[(f0+0)*HH+h] + xv.y*g_Ad1[(f0+1)*HH+h]
           + xv.z*g_Ad1[(f0+2)*HH+h] + xv.w*g_Ad1[(f0+3)*HH+h];
    }
    a_s[i] = s; a_d[i] = d;
}

// ---------------- attention scores from h (layer 2): warp per node ----------------
__global__ void k_attn(const float* __restrict__ h,
                       const float* __restrict__ asrc,
                       const float* __restrict__ adst,
                       float* __restrict__ a_s, float* __restrict__ a_d,
                       int Hn, int NH) {
    int w = (blockIdx.x * blockDim.x + threadIdx.x) >> 5;
    if (w >= NH) return;
    int lane = threadIdx.x & 31;
    int head = w % Hn;
    const float* hp = h + (size_t)w * CC;
    float v0 = hp[lane], v1 = hp[lane + 32];
    float ps = v0 * __ldg(&asrc[head*CC + lane]) + v1 * __ldg(&asrc[head*CC + lane + 32]);
    float pd = v0 * __ldg(&adst[head*CC + lane]) + v1 * __ldg(&adst[head*CC + lane + 32]);
    #pragma unroll
    for (int o = 16; o; o >>= 1) {
        ps += __shfl_down_sync(0xffffffffu, ps, o);
        pd += __shfl_down_sync(0xffffffffu, pd, o);
    }
    if (lane == 0) { a_s[w] = ps; a_d[w] = pd; }
}

// ---------------- GAT aggregation: warp per (node, head), segment softmax + gather ----------------
__global__ void k_agg(const float* __restrict__ h,
                      const float* __restrict__ a_s,
                      const float* __restrict__ a_d,
                      const float* __restrict__ bias,
                      float* __restrict__ out,
                      int Hn, int NH) {
    int w = (blockIdx.x * blockDim.x + threadIdx.x) >> 5;
    if (w >= NH) return;
    int lane = threadIdx.x & 31;
    int n = w / Hn, head = w % Hn;
    int beg = g_rowptr[n], end = g_rowptr[n + 1];
    float adn = a_d[w];

    // pass 1: segment max (lane-parallel over edges)
    float m = -1e30f;
    for (int j = beg + lane; j < end; j += 32) {
        int s = g_csr[j];
        float e = a_s[s * Hn + head] + adn;
        e = e > 0.f ? e : 0.2f * e;
        m = fmaxf(m, e);
    }
    #pragma unroll
    for (int o = 16; o; o >>= 1) m = fmaxf(m, __shfl_xor_sync(0xffffffffu, m, o));

    // pass 2: denom
    float ssum = 0.f;
    for (int j = beg + lane; j < end; j += 32) {
        int s = g_csr[j];
        float e = a_s[s * Hn + head] + adn;
        e = e > 0.f ? e : 0.2f * e;
        ssum += __expf(e - m);
    }
    #pragma unroll
    for (int o = 16; o; o >>= 1) ssum += __shfl_xor_sync(0xffffffffu, ssum, o);
    float inv = 1.f / (ssum + 1e-16f);

    // pass 3: weighted gather (all lanes walk edges; lane = channel)
    float acc0 = 0.f, acc1 = 0.f;
    for (int j = beg; j < end; ++j) {
        int s = g_csr[j];
        float e = a_s[s * Hn + head] + adn;
        e = e > 0.f ? e : 0.2f * e;
        float alpha = __expf(e - m) * inv;
        const float* hp = h + ((size_t)s * Hn + head) * CC;
        acc0 += alpha * hp[lane];
        acc1 += alpha * hp[lane + 32];
    }
    float o0 = acc0 + bias[head*CC + lane];
    float o1 = acc1 + bias[head*CC + lane + 32];
    o0 = o0 > 0.f ? o0 : expm1f(o0);   // fused ELU
    o1 = o1 > 0.f ? o1 : expm1f(o1);
    out[(size_t)w * CC + lane]      = o0;
    out[(size_t)w * CC + lane + 32] = o1;
}

// ---------------- global add pool (batch is sorted); 32-node chunks ----------------
__global__ void k_pool(const int* __restrict__ batch) {
    int c = threadIdx.x;             // 64 channels
    int n0 = blockIdx.x * 32;
    int n1 = n0 + 32; if (n1 > NN) n1 = NN;
    if (n0 >= NN) return;
    float acc = 0.f;
    int cur = batch[n0];
    for (int i = n0; i < n1; i++) {
        int b = batch[i];
        if (b != cur) { atomicAdd(&g_pooled[cur*CC + c], acc); acc = 0.f; cur = b; }
        acc += g_out2[(size_t)i * CC + c];
    }
    atomicAdd(&g_pooled[cur*CC + c], acc);
}

// ---------------- head MLP + log_softmax, one block of 64 per graph ----------------
__global__ void k_head(const float* __restrict__ w1, const float* __restrict__ b1v,
                       const float* __restrict__ w2, const float* __restrict__ b2v,
                       float* __restrict__ out) {
    __shared__ float p[64], zs[64], lg[KK];
    int b = blockIdx.x, t = threadIdx.x;
    p[t] = g_pooled[b*CC + t];
    __syncthreads();
    float z = b1v[t];
    #pragma unroll 16
    for (int k = 0; k < 64; k++) z += p[k] * w1[k*64 + t];
    z = z > 0.f ? z : expm1f(z);
    zs[t] = z;
    __syncthreads();
    if (t < KK) {
        float l = b2v[t];
        #pragma unroll 16
        for (int k = 0; k < 64; k++) l += zs[k] * w2[k*KK + t];
        lg[t] = l;
    }
    __syncthreads();
    if (t < KK) {
        float m = -1e30f;
        #pragma unroll
        for (int k = 0; k < KK; k++) m = fmaxf(m, lg[k]);
        float s = 0.f;
        #pragma unroll
        for (int k = 0; k < KK; k++) s += expf(lg[k] - m);
        out[b*KK + t] = lg[t] - m - logf(s);
    }
}

// ---------------- launch ----------------
extern "C" void kernel_launch(void* const* d_in, const int* in_sizes, int n_in,
                              void* d_out, int out_size) {
    const float* x        = (const float*)d_in[0];
    const int*   ei       = (const int*)  d_in[1];
    const int*   batch    = (const int*)  d_in[2];
    const float* W1       = (const float*)d_in[3];
    const float* att_src1 = (const float*)d_in[4];
    const float* att_dst1 = (const float*)d_in[5];
    const float* b1       = (const float*)d_in[6];
    const float* W2       = (const float*)d_in[7];
    const float* att_src2 = (const float*)d_in[8];
    const float* att_dst2 = (const float*)d_in[9];
    const float* b2       = (const float*)d_in[10];
    const float* l1w      = (const float*)d_in[11];
    const float* l1b      = (const float*)d_in[12];
    const float* l2w      = (const float*)d_in[13];
    const float* l2b      = (const float*)d_in[14];
    float* out = (float*)d_out;

    const int* src = ei;
    const int* dst = ei + EE;

    void *p_h1, *p_out1, *p_h2, *p_out2, *p_as1, *p_ad1, *p_as2, *p_ad2;
    cudaGetSymbolAddress(&p_h1,  g_h1);
    cudaGetSymbolAddress(&p_out1, g_out1);
    cudaGetSymbolAddress(&p_h2,  g_h2);
    cudaGetSymbolAddress(&p_out2, g_out2);
    cudaGetSymbolAddress(&p_as1, g_as1);
    cudaGetSymbolAddress(&p_ad1, g_ad1);
    cudaGetSymbolAddress(&p_as2, g_as2);
    cudaGetSymbolAddress(&p_ad2, g_ad2);
    float* h1   = (float*)p_h1;
    float* out1 = (float*)p_out1;
    float* h2   = (float*)p_h2;
    float* out2 = (float*)p_out2;
    float* as1  = (float*)p_as1;
    float* ad1  = (float*)p_ad1;
    float* as2  = (float*)p_as2;
    float* ad2  = (float*)p_ad2;

    // CSR prefix work
    k_init<<<(NN + 255)/256, 256>>>();
    k_count<<<(EE + 255)/256, 256>>>(dst);
    k_scan<<<1, 1024>>>();

    // GEMM1 in the ncu-captured launch slot: [50000,128]@[128,512], 64-wide tile, 3 CTA/SM
    k_sgemm_t<128,64,16,8,4,3><<<dim3(HC/64, (NN + 127)/128), 256>>>(x, W1, h1, NN, HC, FF);

    // layer-1 attention scores straight from x
    k_prep<<<(FF*HH + 255)/256, 256>>>(W1, att_src1, att_dst1);
    k_attn_x<<<(NN*HH + 255)/256, 256>>>(x, as1, ad1);

    // finish CSR
    k_scatter<<<(ETOT + 255)/256, 256>>>(src, dst);

    // Layer 1 aggregation (verified 3-pass warp-per-(node,head))
    k_agg <<<(NN*HH + 7)/8, 256>>>(h1, as1, ad1, b1, out1, HH, NN*HH);

    // Layer 2: h2 = out1 @ W2  [50000,512]@[512,64] — single wave at 3 CTA/SM
    k_sgemm_t<128,64,16,8,4,3><<<dim3(CC/64, (NN + 127)/128), 256>>>(out1, W2, h2, NN, CC, HC);
    k_attn<<<(NN + 7)/8, 256>>>(h2, att_src2, att_dst2, as2, ad2, 1, NN);
    k_agg <<<(NN + 7)/8, 256>>>(h2, as2, ad2, b2, out2, 1, NN);

    // Pool + head
    k_pool<<<(NN + 31)/32, 64>>>(batch);
    k_head<<<BB, 64>>>(l1w, l1b, l2w, l2b, out);
}

// round 15
// speedup vs baseline: 1.3384x; 1.0029x over previous
#include <cuda_runtime.h>
#include <math.h>

#define NN 50000
#define EE 400000
#define FF 128
#define HH 8
#define CC 64
#define BB 64
#define KK 10
#define HC (HH*CC)     /* 512 */
#define ETOT (EE+NN)   /* 450000 edges incl. self loops */

// ---------------- scratch (device globals; no allocation allowed) ----------------
__device__ __align__(16) float g_h1[(size_t)NN*HC];    // x@W1
__device__ __align__(16) float g_out1[(size_t)NN*HC];  // elu(gat1)
__device__ __align__(16) float g_h2[(size_t)NN*CC];    // out1@W2
__device__ __align__(16) float g_out2[(size_t)NN*CC];  // elu(gat2)
__device__ __align__(16) float g_as1[NN*HH];
__device__ __align__(16) float g_ad1[NN*HH];
__device__ __align__(16) float g_as2[NN];
__device__ __align__(16) float g_ad2[NN];
__device__ __align__(16) float g_pooled[BB*CC];
__device__ __align__(16) float g_As1[FF*HH];
__device__ __align__(16) float g_Ad1[FF*HH];
__device__ int g_deg[NN];
__device__ int g_rowptr[NN+1];
__device__ int g_fill[NN];
__device__ int g_csr[ETOT];

// ---------------- f32x2 packed helpers (Blackwell FFMA2) ----------------
__device__ __forceinline__ unsigned long long pk2(float lo, float hi) {
    unsigned long long r;
    asm("mov.b64 %0, {%1, %2};" : "=l"(r) : "r"(__float_as_uint(lo)), "r"(__float_as_uint(hi)));
    return r;
}
__device__ __forceinline__ void unpk2(unsigned long long v, float& lo, float& hi) {
    unsigned int a, b;
    asm("mov.b64 {%0, %1}, %2;" : "=r"(a), "=r"(b) : "l"(v));
    lo = __uint_as_float(a); hi = __uint_as_float(b);
}
__device__ __forceinline__ unsigned long long ffma2(unsigned long long a,
                                                    unsigned long long b,
                                                    unsigned long long c) {
    unsigned long long d;
    asm("fma.rn.f32x2 %0, %1, %2, %3;" : "=l"(d) : "l"(a), "l"(b), "l"(c));
    return d;
}
// cp.async 16B (zero-fills when sz==0)
__device__ __forceinline__ void cp16(void* dst, const void* src, int sz) {
    unsigned int d = (unsigned int)__cvta_generic_to_shared(dst);
    asm volatile("cp.async.cg.shared.global [%0], [%1], 16, %2;" :: "r"(d), "l"(src), "r"(sz));
}

// ---------------- CSR build ----------------
__global__ void k_init() {
    int i = blockIdx.x*blockDim.x + threadIdx.x;
    if (i < NN) { g_deg[i] = 1; g_fill[i] = 0; }
    if (i < BB*CC) g_pooled[i] = 0.f;
}

__global__ void k_count(const int* __restrict__ dst) {
    int i = blockIdx.x*blockDim.x + threadIdx.x;
    if (i < EE) atomicAdd(&g_deg[dst[i]], 1);
}

__global__ void k_scan() {
    __shared__ int sh[1024];
    int t = threadIdx.x;
    const int chunk = (NN + 1023) / 1024;
    int beg = t * chunk;
    int end = beg + chunk; if (end > NN) end = NN;
    int sum = 0;
    for (int i = beg; i < end; i++) sum += g_deg[i];
    sh[t] = sum;
    __syncthreads();
    for (int off = 1; off < 1024; off <<= 1) {
        int v = (t >= off) ? sh[t - off] : 0;
        __syncthreads();
        sh[t] += v;
        __syncthreads();
    }
    int run = (t == 0) ? 0 : sh[t - 1];
    for (int i = beg; i < end; i++) { g_rowptr[i] = run; run += g_deg[i]; }
    if (t == 1023) g_rowptr[NN] = sh[1023];
}

__global__ void k_scatter(const int* __restrict__ src, const int* __restrict__ dst) {
    int i = blockIdx.x*blockDim.x + threadIdx.x;
    if (i >= ETOT) return;
    int d, s;
    if (i < EE) { d = dst[i]; s = src[i]; }
    else        { d = i - EE; s = d; }
    int pos = g_rowptr[d] + atomicAdd(&g_fill[d], 1);
    g_csr[pos] = s;
}

// ---------------- SGEMM (cp.async staged): C = A @ B ----------------
// A staged packed-k: As4[BK/4][BM] float4 (4 k's per node) -> no transpose needed.
// B staged row-major. Double-buffered via cp.async commit/wait groups.
template<int BM,int BN,int BK,int TM,int TN,int MINB>
__global__ void __launch_bounds__(256, MINB)
k_sgemm_ca(const float* __restrict__ A, const float* __restrict__ B,
           float* __restrict__ C, int M, int N, int K)
{
    constexpr int THREADS = (BM/TM)*(BN/TN);   // 256
    constexpr int KQ  = BK/4;                  // float4 k-groups
    constexpr int AL  = BM*KQ/THREADS;         // A cp.async per thread
    constexpr int BL  = BK*(BN/4)/THREADS;     // B cp.async per thread
    constexpr int GM  = TM/4;
    constexpr int GN  = TN/4;
    constexpr int TN2 = TN/2;

    __shared__ float4 As4[2][KQ][BM];
    __shared__ float4 Bs4[2][BK][BN/4];

    const int bm = blockIdx.y*BM, bn = blockIdx.x*BN;
    const int tid = threadIdx.x;
    const int tx  = tid % (BN/TN);
    const int ty  = tid / (BN/TN);
    const int nt  = K/BK;

    auto issue = [&](int k0, int buf) {
        #pragma unroll
        for (int l = 0; l < AL; l++) {
            int i = tid + l*THREADS;
            int m = i / KQ, kk = i % KQ;
            int row = bm + m;
            int sz = 16;
            if (row >= M) { row = M - 1; sz = 0; }
            cp16(&As4[buf][kk][m], A + (size_t)row*K + k0 + kk*4, sz);
        }
        #pragma unroll
        for (int l = 0; l < BL; l++) {
            int i = tid + l*THREADS;
            int kk = i / (BN/4), c = i % (BN/4);
            cp16(&Bs4[buf][kk][c], B + (size_t)(k0+kk)*N + bn + c*4, 16);
        }
        asm volatile("cp.async.commit_group;" ::: "memory");
    };

    unsigned long long acc[TM][TN2];
    #pragma unroll
    for (int i = 0; i < TM; i++)
        #pragma unroll
        for (int j = 0; j < TN2; j++) acc[i][j] = 0ull;

    issue(0, 0);
    asm volatile("cp.async.wait_group 0;" ::: "memory");
    __syncthreads();

    for (int t = 0; t < nt; t++) {
        int buf = t & 1;
        if (t + 1 < nt) issue((t+1)*BK, buf ^ 1);

        #pragma unroll
        for (int kq = 0; kq < KQ; kq++) {
            float4 A4[GM*4];
            #pragma unroll
            for (int g = 0; g < GM; g++)
                #pragma unroll
                for (int r = 0; r < 4; r++)
                    A4[g*4+r] = As4[buf][kq][g*(BM/2) + ty*4 + r];
            #pragma unroll
            for (int kin = 0; kin < 4; kin++) {
                unsigned long long bp[GN*2];
                #pragma unroll
                for (int g = 0; g < GN; g++) {
                    float4 v = Bs4[buf][kq*4+kin][g*(BN/8) + tx];
                    bp[g*2+0] = pk2(v.x, v.y);
                    bp[g*2+1] = pk2(v.z, v.w);
                }
                #pragma unroll
                for (int i = 0; i < TM; i++) {
                    float av = (kin == 0) ? A4[i].x : (kin == 1) ? A4[i].y
                             : (kin == 2) ? A4[i].z : A4[i].w;
                    unsigned long long ad = pk2(av, av);
                    #pragma unroll
                    for (int j = 0; j < TN2; j++)
                        acc[i][j] = ffma2(ad, bp[j], acc[i][j]);
                }
            }
        }
        if (t + 1 < nt) asm volatile("cp.async.wait_group 0;" ::: "memory");
        __syncthreads();
    }

    #pragma unroll
    for (int g = 0; g < GM; g++) {
        #pragma unroll
        for (int i = 0; i < 4; i++) {
            int row = bm + g*(BM/2) + ty*4 + i;
            if (row >= M) continue;
            #pragma unroll
            for (int h = 0; h < GN; h++) {
                float4 v;
                unpk2(acc[g*4+i][h*2+0], v.x, v.y);
                unpk2(acc[g*4+i][h*2+1], v.z, v.w);
                *(float4*)(C + (size_t)row*N + bn + h*(BN/2) + tx*4) = v;
            }
        }
    }
}

// ---------------- SGEMM (register staged, verified) for GEMM2 ----------------
template<int BM,int BN,int BK,int TM,int TN,int MINB>
__global__ void __launch_bounds__(256, MINB)
k_sgemm_t(const float* __restrict__ A, const float* __restrict__ B,
          float* __restrict__ C, int M, int N, int K)
{
    constexpr int THREADS = (BM/TM)*(BN/TN);
    constexpr int AF4 = BM*BK/(4*THREADS);
    constexpr int BF4 = BK*BN/(4*THREADS);
    constexpr int AR  = BK/4;
    constexpr int BR  = BN/4;
    constexpr int GM  = TM/4;
    constexpr int GN  = TN/4;
    constexpr int TN2 = TN/2;

    __shared__ float As[2][BK][BM];
    __shared__ float Bs[2][BK][BN];

    const int bm = blockIdx.y*BM, bn = blockIdx.x*BN;
    const int tid = threadIdx.x;
    const int tx  = tid % (BN/TN);
    const int ty  = tid / (BN/TN);

    float4 ra[AF4], rb[BF4];
    const int nt = K/BK;

    auto ldg = [&](int k0) {
        #pragma unroll
        for (int i = 0; i < AF4; i++) {
            int idx = tid + i*THREADS;
            int r = idx / AR, c4 = (idx % AR)*4;
            int row = bm + r;
            ra[i] = (row < M) ? *(const float4*)(A + (size_t)row*K + k0 + c4)
                              : make_float4(0.f,0.f,0.f,0.f);
        }
        #pragma unroll
        for (int i = 0; i < BF4; i++) {
            int idx = tid + i*THREADS;
            int kk = idx / BR, c4 = (idx % BR)*4;
            rb[i] = *(const float4*)(B + (size_t)(k0+kk)*N + bn + c4);
        }
    };
    auto sts = [&](int buf) {
        #pragma unroll
        for (int i = 0; i < AF4; i++) {
            int idx = tid + i*THREADS;
            int r = idx / AR, c4 = (idx % AR)*4;
            As[buf][c4+0][r] = ra[i].x; As[buf][c4+1][r] = ra[i].y;
            As[buf][c4+2][r] = ra[i].z; As[buf][c4+3][r] = ra[i].w;
        }
        #pragma unroll
        for (int i = 0; i < BF4; i++) {
            int idx = tid + i*THREADS;
            int kk = idx / BR, c4 = (idx % BR)*4;
            *(float4*)&Bs[buf][kk][c4] = rb[i];
        }
    };

    unsigned long long acc[TM][TN2];
    #pragma unroll
    for (int i = 0; i < TM; i++)
        #pragma unroll
        for (int j = 0; j < TN2; j++) acc[i][j] = 0ull;

    ldg(0);
    sts(0);
    __syncthreads();

    for (int t = 0; t < nt; t++) {
        int buf = t & 1;
        if (t + 1 < nt) ldg((t+1)*BK);
        #pragma unroll
        for (int k = 0; k < BK; k++) {
            float a[TM];
            unsigned long long bp[TN2];
            #pragma unroll
            for (int g = 0; g < GM; g++) {
                float4 v = *(const float4*)&As[buf][k][g*(BM/2) + ty*4];
                a[g*4+0]=v.x; a[g*4+1]=v.y; a[g*4+2]=v.z; a[g*4+3]=v.w;
            }
            #pragma unroll
            for (int g = 0; g < GN; g++) {
                float4 v = *(const float4*)&Bs[buf][k][g*(BN/2) + tx*4];
                bp[g*2+0] = pk2(v.x, v.y);
                bp[g*2+1] = pk2(v.z, v.w);
            }
            #pragma unroll
            for (int i = 0; i < TM; i++) {
                unsigned long long ad = pk2(a[i], a[i]);
                #pragma unroll
                for (int j = 0; j < TN2; j++)
                    acc[i][j] = ffma2(ad, bp[j], acc[i][j]);
            }
        }
        if (t + 1 < nt) sts(buf ^ 1);
        __syncthreads();
    }

    #pragma unroll
    for (int g = 0; g < GM; g++) {
        #pragma unroll
        for (int i = 0; i < 4; i++) {
            int row = bm + g*(BM/2) + ty*4 + i;
            if (row >= M) continue;
            #pragma unroll
            for (int h = 0; h < GN; h++) {
                float4 v;
                unpk2(acc[g*4+i][h*2+0], v.x, v.y);
                unpk2(acc[g*4+i][h*2+1], v.z, v.w);
                *(float4*)(C + (size_t)row*N + bn + h*(BN/2) + tx*4) = v;
            }
        }
    }
}

// ---------------- layer-1 attention prep ----------------
__global__ void k_prep(const float* __restrict__ W,
                       const float* __restrict__ atts, const float* __restrict__ attd) {
    int i = blockIdx.x*blockDim.x + threadIdx.x;
    if (i >= FF*HH) return;
    int f = i / HH, h = i % HH;
    const float* wrow = W + (size_t)f*HC + h*CC;
    float s = 0.f, d = 0.f;
    #pragma unroll 8
    for (int c = 0; c < CC; c++) {
        float w = wrow[c];
        s += w * atts[h*CC + c];
        d += w * attd[h*CC + c];
    }
    g_As1[f*HH + h] = s;
    g_Ad1[f*HH + h] = d;
}

__global__ void k_attn_x(const float* __restrict__ x,
                         float* __restrict__ a_s, float* __restrict__ a_d) {
    int i = blockIdx.x*blockDim.x + threadIdx.x;
    if (i >= NN*HH) return;
    int n = i >> 3, h = i & 7;
    const float* xr = x + (size_t)n*FF;
    float s = 0.f, d = 0.f;
    #pragma unroll
    for (int f0 = 0; f0 < FF; f0 += 4) {
        float4 xv = *(const float4*)(xr + f0);
        s += xv.x*g_As1[(f0+0)*HH+h] + xv.y*g_As1[(f0+1)*HH+h]
           + xv.z*g_As1[(f0+2)*HH+h] + xv.w*g_As1[(f0+3)*HH+h];
        d += xv.x*g_Ad1[(f0+0)*HH+h] + xv.y*g_Ad1[(f0+1)*HH+h]
           + xv.z*g_Ad1[(f0+2)*HH+h] + xv.w*g_Ad1[(f0+3)*HH+h];
    }
    a_s[i] = s; a_d[i] = d;
}

// ---------------- attention scores from h (layer 2) ----------------
__global__ void k_attn(const float* __restrict__ h,
                       const float* __restrict__ asrc,
                       const float* __restrict__ adst,
                       float* __restrict__ a_s, float* __restrict__ a_d,
                       int Hn, int NH) {
    int w = (blockIdx.x * blockDim.x + threadIdx.x) >> 5;
    if (w >= NH) return;
    int lane = threadIdx.x & 31;
    int head = w % Hn;
    const float* hp = h + (size_t)w * CC;
    float v0 = hp[lane], v1 = hp[lane + 32];
    float ps = v0 * __ldg(&asrc[head*CC + lane]) + v1 * __ldg(&asrc[head*CC + lane + 32]);
    float pd = v0 * __ldg(&adst[head*CC + lane]) + v1 * __ldg(&adst[head*CC + lane + 32]);
    #pragma unroll
    for (int o = 16; o; o >>= 1) {
        ps += __shfl_down_sync(0xffffffffu, ps, o);
        pd += __shfl_down_sync(0xffffffffu, pd, o);
    }
    if (lane == 0) { a_s[w] = ps; a_d[w] = pd; }
}

// ---------------- GAT aggregation: warp per (node, head) ----------------
__global__ void k_agg(const float* __restrict__ h,
                      const float* __restrict__ a_s,
                      const float* __restrict__ a_d,
                      const float* __restrict__ bias,
                      float* __restrict__ out,
                      int Hn, int NH) {
    int w = (blockIdx.x * blockDim.x + threadIdx.x) >> 5;
    if (w >= NH) return;
    int lane = threadIdx.x & 31;
    int n = w / Hn, head = w % Hn;
    int beg = g_rowptr[n], end = g_rowptr[n + 1];
    float adn = a_d[w];

    float m = -1e30f;
    for (int j = beg + lane; j < end; j += 32) {
        int s = g_csr[j];
        float e = a_s[s * Hn + head] + adn;
        e = e > 0.f ? e : 0.2f * e;
        m = fmaxf(m, e);
    }
    #pragma unroll
    for (int o = 16; o; o >>= 1) m = fmaxf(m, __shfl_xor_sync(0xffffffffu, m, o));

    float ssum = 0.f;
    for (int j = beg + lane; j < end; j += 32) {
        int s = g_csr[j];
        float e = a_s[s * Hn + head] + adn;
        e = e > 0.f ? e : 0.2f * e;
        ssum += __expf(e - m);
    }
    #pragma unroll
    for (int o = 16; o; o >>= 1) ssum += __shfl_xor_sync(0xffffffffu, ssum, o);
    float inv = 1.f / (ssum + 1e-16f);

    float acc0 = 0.f, acc1 = 0.f;
    for (int j = beg; j < end; ++j) {
        int s = g_csr[j];
        float e = a_s[s * Hn + head] + adn;
        e = e > 0.f ? e : 0.2f * e;
        float alpha = __expf(e - m) * inv;
        const float* hp = h + ((size_t)s * Hn + head) * CC;
        acc0 += alpha * hp[lane];
        acc1 += alpha * hp[lane + 32];
    }
    float o0 = acc0 + bias[head*CC + lane];
    float o1 = acc1 + bias[head*CC + lane + 32];
    o0 = o0 > 0.f ? o0 : expm1f(o0);
    o1 = o1 > 0.f ? o1 : expm1f(o1);
    out[(size_t)w * CC + lane]      = o0;
    out[(size_t)w * CC + lane + 32] = o1;
}

// ---------------- global add pool (batch is sorted); 32-node chunks ----------------
__global__ void k_pool(const int* __restrict__ batch) {
    int c = threadIdx.x;
    int n0 = blockIdx.x * 32;
    int n1 = n0 + 32; if (n1 > NN) n1 = NN;
    if (n0 >= NN) return;
    float acc = 0.f;
    int cur = batch[n0];
    for (int i = n0; i < n1; i++) {
        int b = batch[i];
        if (b != cur) { atomicAdd(&g_pooled[cur*CC + c], acc); acc = 0.f; cur = b; }
        acc += g_out2[(size_t)i * CC + c];
    }
    atomicAdd(&g_pooled[cur*CC + c], acc);
}

// ---------------- head MLP + log_softmax ----------------
__global__ void k_head(const float* __restrict__ w1, const float* __restrict__ b1v,
                       const float* __restrict__ w2, const float* __restrict__ b2v,
                       float* __restrict__ out) {
    __shared__ float p[64], zs[64], lg[KK];
    int b = blockIdx.x, t = threadIdx.x;
    p[t] = g_pooled[b*CC + t];
    __syncthreads();
    float z = b1v[t];
    #pragma unroll 16
    for (int k = 0; k < 64; k++) z += p[k] * w1[k*64 + t];
    z = z > 0.f ? z : expm1f(z);
    zs[t] = z;
    __syncthreads();
    if (t < KK) {
        float l = b2v[t];
        #pragma unroll 16
        for (int k = 0; k < 64; k++) l += zs[k] * w2[k*KK + t];
        lg[t] = l;
    }
    __syncthreads();
    if (t < KK) {
        float m = -1e30f;
        #pragma unroll
        for (int k = 0; k < KK; k++) m = fmaxf(m, lg[k]);
        float s = 0.f;
        #pragma unroll
        for (int k = 0; k < KK; k++) s += expf(lg[k] - m);
        out[b*KK + t] = lg[t] - m - logf(s);
    }
}

// ---------------- launch ----------------
extern "C" void kernel_launch(void* const* d_in, const int* in_sizes, int n_in,
                              void* d_out, int out_size) {
    const float* x        = (const float*)d_in[0];
    const int*   ei       = (const int*)  d_in[1];
    const int*   batch    = (const int*)  d_in[2];
    const float* W1       = (const float*)d_in[3];
    const float* att_src1 = (const float*)d_in[4];
    const float* att_dst1 = (const float*)d_in[5];
    const float* b1       = (const float*)d_in[6];
    const float* W2       = (const float*)d_in[7];
    const float* att_src2 = (const float*)d_in[8];
    const float* att_dst2 = (const float*)d_in[9];
    const float* b2       = (const float*)d_in[10];
    const float* l1w      = (const float*)d_in[11];
    const float* l1b      = (const float*)d_in[12];
    const float* l2w      = (const float*)d_in[13];
    const float* l2b      = (const float*)d_in[14];
    float* out = (float*)d_out;

    const int* src = ei;
    const int* dst = ei + EE;

    void *p_h1, *p_out1, *p_h2, *p_out2, *p_as1, *p_ad1, *p_as2, *p_ad2;
    cudaGetSymbolAddress(&p_h1,  g_h1);
    cudaGetSymbolAddress(&p_out1, g_out1);
    cudaGetSymbolAddress(&p_h2,  g_h2);
    cudaGetSymbolAddress(&p_out2, g_out2);
    cudaGetSymbolAddress(&p_as1, g_as1);
    cudaGetSymbolAddress(&p_ad1, g_ad1);
    cudaGetSymbolAddress(&p_as2, g_as2);
    cudaGetSymbolAddress(&p_ad2, g_ad2);
    float* h1   = (float*)p_h1;
    float* out1 = (float*)p_out1;
    float* h2   = (float*)p_h2;
    float* out2 = (float*)p_out2;
    float* as1  = (float*)p_as1;
    float* ad1  = (float*)p_ad1;
    float* as2  = (float*)p_as2;
    float* ad2  = (float*)p_ad2;

    // CSR prefix work
    k_init<<<(NN + 255)/256, 256>>>();
    k_count<<<(EE + 255)/256, 256>>>(dst);
    k_scan<<<1, 1024>>>();

    // GEMM1 in the ncu-captured slot: [50000,128]@[128,512], cp.async, BN=128, 2 CTA/SM
    k_sgemm_ca<128,128,16,8,8,2><<<dim3(HC/128, (NN + 127)/128), 256>>>(x, W1, h1, NN, HC, FF);

    // layer-1 attention scores straight from x
    k_prep<<<(FF*HH + 255)/256, 256>>>(W1, att_src1, att_dst1);
    k_attn_x<<<(NN*HH + 255)/256, 256>>>(x, as1, ad1);

    // finish CSR
    k_scatter<<<(ETOT + 255)/256, 256>>>(src, dst);

    // Layer 1 aggregation (verified 3-pass warp-per-(node,head))
    k_agg <<<(NN*HH + 7)/8, 256>>>(h1, as1, ad1, b1, out1, HH, NN*HH);

    // Layer 2: [50000,512]@[512,64] — measured-good register-staged BN=64, 3 CTA/SM
    k_sgemm_t<128,64,16,8,4,3><<<dim3(CC/64, (NN + 127)/128), 256>>>(out1, W2, h2, NN, CC, HC);
    k_attn<<<(NN + 7)/8, 256>>>(h2, att_src2, att_dst2, as2, ad2, 1, NN);
    k_agg <<<(NN + 7)/8, 256>>>(h2, as2, ad2, b2, out2, 1, NN);

    // Pool + head
    k_pool<<<(NN + 31)/32, 64>>>(batch);
    k_head<<<BB, 64>>>(l1w, l1b, l2w, l2b, out);
}

// round 16
// speedup vs baseline: 1.4623x; 1.0926x over previous
#include <cuda_runtime.h>
#include <math.h>

#define NN 50000
#define EE 400000
#define FF 128
#define HH 8
#define CC 64
#define BB 64
#define KK 10
#define HC (HH*CC)     /* 512 */
#define ETOT (EE+NN)   /* 450000 edges incl. self loops */

// ---------------- scratch (device globals; no allocation allowed) ----------------
__device__ __align__(16) float g_h1[(size_t)NN*HC];
__device__ __align__(16) float g_out1[(size_t)NN*HC];
__device__ __align__(16) float g_h2[(size_t)NN*CC];
__device__ __align__(16) float g_out2[(size_t)NN*CC];
__device__ __align__(16) float g_as1[NN*HH];
__device__ __align__(16) float g_ad1[NN*HH];
__device__ __align__(16) float g_as2[NN];
__device__ __align__(16) float g_ad2[NN];
__device__ __align__(16) float g_pooled[BB*CC];
__device__ __align__(16) float g_As1[FF*HH];
__device__ __align__(16) float g_Ad1[FF*HH];
__device__ int g_deg[NN];
__device__ int g_rowptr[NN+1];
__device__ int g_fill[NN];
__device__ int g_csr[ETOT];

// ---------------- f32x2 packed helpers (Blackwell FFMA2) ----------------
__device__ __forceinline__ unsigned long long pk2(float lo, float hi) {
    unsigned long long r;
    asm("mov.b64 %0, {%1, %2};" : "=l"(r) : "r"(__float_as_uint(lo)), "r"(__float_as_uint(hi)));
    return r;
}
__device__ __forceinline__ void unpk2(unsigned long long v, float& lo, float& hi) {
    unsigned int a, b;
    asm("mov.b64 {%0, %1}, %2;" : "=r"(a), "=r"(b) : "l"(v));
    lo = __uint_as_float(a); hi = __uint_as_float(b);
}
__device__ __forceinline__ unsigned long long ffma2(unsigned long long a,
                                                    unsigned long long b,
                                                    unsigned long long c) {
    unsigned long long d;
    asm("fma.rn.f32x2 %0, %1, %2, %3;" : "=l"(d) : "l"(a), "l"(b), "l"(c));
    return d;
}

// ---------------- CSR build ----------------
__global__ void k_init() {
    int i = blockIdx.x*blockDim.x + threadIdx.x;
    if (i < NN) { g_deg[i] = 1; g_fill[i] = 0; }
    if (i < BB*CC) g_pooled[i] = 0.f;
}

__global__ void k_count(const int* __restrict__ dst) {
    int i = blockIdx.x*blockDim.x + threadIdx.x;
    if (i < EE) atomicAdd(&g_deg[dst[i]], 1);
}

__global__ void k_scan() {
    __shared__ int sh[1024];
    int t = threadIdx.x;
    const int chunk = (NN + 1023) / 1024;
    int beg = t * chunk;
    int end = beg + chunk; if (end > NN) end = NN;
    int sum = 0;
    for (int i = beg; i < end; i++) sum += g_deg[i];
    sh[t] = sum;
    __syncthreads();
    for (int off = 1; off < 1024; off <<= 1) {
        int v = (t >= off) ? sh[t - off] : 0;
        __syncthreads();
        sh[t] += v;
        __syncthreads();
    }
    int run = (t == 0) ? 0 : sh[t - 1];
    for (int i = beg; i < end; i++) { g_rowptr[i] = run; run += g_deg[i]; }
    if (t == 1023) g_rowptr[NN] = sh[1023];
}

__global__ void k_scatter(const int* __restrict__ src, const int* __restrict__ dst) {
    int i = blockIdx.x*blockDim.x + threadIdx.x;
    if (i >= ETOT) return;
    int d, s;
    if (i < EE) { d = dst[i]; s = src[i]; }
    else        { d = i - EE; s = d; }
    int pos = g_rowptr[d] + atomicAdd(&g_fill[d], 1);
    g_csr[pos] = s;
}

// ---------------- SGEMM (register staged, measured-best): C = A @ B ----------------
template<int BM,int BN,int BK,int TM,int TN,int MINB>
__global__ void __launch_bounds__(256, MINB)
k_sgemm_t(const float* __restrict__ A, const float* __restrict__ B,
          float* __restrict__ C, int M, int N, int K)
{
    constexpr int THREADS = (BM/TM)*(BN/TN);
    constexpr int AF4 = BM*BK/(4*THREADS);
    constexpr int BF4 = BK*BN/(4*THREADS);
    constexpr int AR  = BK/4;
    constexpr int BR  = BN/4;
    constexpr int GM  = TM/4;
    constexpr int GN  = TN/4;
    constexpr int TN2 = TN/2;

    __shared__ float As[2][BK][BM];
    __shared__ float Bs[2][BK][BN];

    const int bm = blockIdx.y*BM, bn = blockIdx.x*BN;
    const int tid = threadIdx.x;
    const int tx  = tid % (BN/TN);
    const int ty  = tid / (BN/TN);

    float4 ra[AF4], rb[BF4];
    const int nt = K/BK;

    auto ldg = [&](int k0) {
        #pragma unroll
        for (int i = 0; i < AF4; i++) {
            int idx = tid + i*THREADS;
            int r = idx / AR, c4 = (idx % AR)*4;
            int row = bm + r;
            ra[i] = (row < M) ? *(const float4*)(A + (size_t)row*K + k0 + c4)
                              : make_float4(0.f,0.f,0.f,0.f);
        }
        #pragma unroll
        for (int i = 0; i < BF4; i++) {
            int idx = tid + i*THREADS;
            int kk = idx / BR, c4 = (idx % BR)*4;
            rb[i] = *(const float4*)(B + (size_t)(k0+kk)*N + bn + c4);
        }
    };
    auto sts = [&](int buf) {
        #pragma unroll
        for (int i = 0; i < AF4; i++) {
            int idx = tid + i*THREADS;
            int r = idx / AR, c4 = (idx % AR)*4;
            As[buf][c4+0][r] = ra[i].x; As[buf][c4+1][r] = ra[i].y;
            As[buf][c4+2][r] = ra[i].z; As[buf][c4+3][r] = ra[i].w;
        }
        #pragma unroll
        for (int i = 0; i < BF4; i++) {
            int idx = tid + i*THREADS;
            int kk = idx / BR, c4 = (idx % BR)*4;
            *(float4*)&Bs[buf][kk][c4] = rb[i];
        }
    };

    unsigned long long acc[TM][TN2];
    #pragma unroll
    for (int i = 0; i < TM; i++)
        #pragma unroll
        for (int j = 0; j < TN2; j++) acc[i][j] = 0ull;

    ldg(0);
    sts(0);
    __syncthreads();

    for (int t = 0; t < nt; t++) {
        int buf = t & 1;
        if (t + 1 < nt) ldg((t+1)*BK);
        #pragma unroll
        for (int k = 0; k < BK; k++) {
            float a[TM];
            unsigned long long bp[TN2];
            #pragma unroll
            for (int g = 0; g < GM; g++) {
                float4 v = *(const float4*)&As[buf][k][g*(BM/2) + ty*4];
                a[g*4+0]=v.x; a[g*4+1]=v.y; a[g*4+2]=v.z; a[g*4+3]=v.w;
            }
            #pragma unroll
            for (int g = 0; g < GN; g++) {
                float4 v = *(const float4*)&Bs[buf][k][g*(BN/2) + tx*4];
                bp[g*2+0] = pk2(v.x, v.y);
                bp[g*2+1] = pk2(v.z, v.w);
            }
            #pragma unroll
            for (int i = 0; i < TM; i++) {
                unsigned long long ad = pk2(a[i], a[i]);
                #pragma unroll
                for (int j = 0; j < TN2; j++)
                    acc[i][j] = ffma2(ad, bp[j], acc[i][j]);
            }
        }
        if (t + 1 < nt) sts(buf ^ 1);
        __syncthreads();
    }

    #pragma unroll
    for (int g = 0; g < GM; g++) {
        #pragma unroll
        for (int i = 0; i < 4; i++) {
            int row = bm + g*(BM/2) + ty*4 + i;
            if (row >= M) continue;
            #pragma unroll
            for (int h = 0; h < GN; h++) {
                float4 v;
                unpk2(acc[g*4+i][h*2+0], v.x, v.y);
                unpk2(acc[g*4+i][h*2+1], v.z, v.w);
                *(float4*)(C + (size_t)row*N + bn + h*(BN/2) + tx*4) = v;
            }
        }
    }
}

// ---------------- layer-1 attention prep ----------------
__global__ void k_prep(const float* __restrict__ W,
                       const float* __restrict__ atts, const float* __restrict__ attd) {
    int i = blockIdx.x*blockDim.x + threadIdx.x;
    if (i >= FF*HH) return;
    int f = i / HH, h = i % HH;
    const float* wrow = W + (size_t)f*HC + h*CC;
    float s = 0.f, d = 0.f;
    #pragma unroll 8
    for (int c = 0; c < CC; c++) {
        float w = wrow[c];
        s += w * atts[h*CC + c];
        d += w * attd[h*CC + c];
    }
    g_As1[f*HH + h] = s;
    g_Ad1[f*HH + h] = d;
}

// a_s1[n,h] = x[n,:] . As1[:,h]
__global__ void k_attn_x(const float* __restrict__ x,
                         float* __restrict__ a_s, float* __restrict__ a_d) {
    int i = blockIdx.x*blockDim.x + threadIdx.x;
    if (i >= NN*HH) return;
    int n = i >> 3, h = i & 7;
    const float* xr = x + (size_t)n*FF;
    float s = 0.f, d = 0.f;
    #pragma unroll
    for (int f0 = 0; f0 < FF; f0 += 4) {
        float4 xv = *(const float4*)(xr + f0);
        s += xv.x*g_As1[(f0+0)*HH+h] + xv.y*g_As1[(f0+1)*HH+h]
           + xv.z*g_As1[(f0+2)*HH+h] + xv.w*g_As1[(f0+3)*HH+h];
        d += xv.x*g_Ad1[(f0+0)*HH+h] + xv.y*g_Ad1[(f0+1)*HH+h]
           + xv.z*g_Ad1[(f0+2)*HH+h] + xv.w*g_Ad1[(f0+3)*HH+h];
    }
    a_s[i] = s; a_d[i] = d;
}

// ---------------- attention scores from h (layer 2) ----------------
__global__ void k_attn(const float* __restrict__ h,
                       const float* __restrict__ asrc,
                       const float* __restrict__ adst,
                       float* __restrict__ a_s, float* __restrict__ a_d,
                       int Hn, int NH) {
    int w = (blockIdx.x * blockDim.x + threadIdx.x) >> 5;
    if (w >= NH) return;
    int lane = threadIdx.x & 31;
    int head = w % Hn;
    const float* hp = h + (size_t)w * CC;
    float v0 = hp[lane], v1 = hp[lane + 32];
    float ps = v0 * __ldg(&asrc[head*CC + lane]) + v1 * __ldg(&asrc[head*CC + lane + 32]);
    float pd = v0 * __ldg(&adst[head*CC + lane]) + v1 * __ldg(&adst[head*CC + lane + 32]);
    #pragma unroll
    for (int o = 16; o; o >>= 1) {
        ps += __shfl_down_sync(0xffffffffu, ps, o);
        pd += __shfl_down_sync(0xffffffffu, pd, o);
    }
    if (lane == 0) { a_s[w] = ps; a_d[w] = pd; }
}

// ---------------- GAT aggregation: warp per (node,head), smem-cached edges ----------------
// Pass A: each edge loaded ONCE (csr + a_s -> smem). Pass B: softmax in smem.
// Pass C: serial gather reads s/alpha from smem (LDS 29cy) -> only the h-row
// load touches L2 per edge. deg>64 falls back to the original 3-pass path.
#define SDEG 64
__global__ void __launch_bounds__(256) k_agg(const float* __restrict__ h,
                      const float* __restrict__ a_s,
                      const float* __restrict__ a_d,
                      const float* __restrict__ bias,
                      float* __restrict__ out,
                      int Hn, int NH) {
    const unsigned FULL = 0xffffffffu;
    __shared__ float s_e[8][SDEG];
    __shared__ int   s_s[8][SDEG];
    int w = (blockIdx.x * blockDim.x + threadIdx.x) >> 5;
    if (w >= NH) return;
    int wb = threadIdx.x >> 5;
    int lane = threadIdx.x & 31;
    int n = w / Hn, head = w % Hn;
    int beg = g_rowptr[n], end = g_rowptr[n + 1];
    int deg = end - beg;
    float adn = a_d[w];

    if (deg <= SDEG) {
        float* se = s_e[wb];
        int*   ss = s_s[wb];
        // pass A: single load of each edge, logits into smem, running max
        float m = -1e30f;
        for (int j = lane; j < deg; j += 32) {
            int s = g_csr[beg + j];
            ss[j] = s;
            float e = __ldg(&a_s[s * Hn + head]) + adn;
            e = e > 0.f ? e : 0.2f * e;
            se[j] = e;
            m = fmaxf(m, e);
        }
        #pragma unroll
        for (int o = 16; o; o >>= 1) m = fmaxf(m, __shfl_xor_sync(FULL, m, o));
        __syncwarp();
        // pass B: p = exp(e-m), sum, store p in smem
        float ssum = 0.f;
        for (int j = lane; j < deg; j += 32) {
            float p = __expf(se[j] - m);
            se[j] = p;
            ssum += p;
        }
        #pragma unroll
        for (int o = 16; o; o >>= 1) ssum += __shfl_xor_sync(FULL, ssum, o);
        float inv = 1.f / (ssum + 1e-16f);
        __syncwarp();
        // pass C: gather; s/alpha from smem, only h-row load hits L2
        float acc0 = 0.f, acc1 = 0.f;
        for (int j = 0; j < deg; ++j) {
            float alpha = se[j] * inv;
            int s = ss[j];
            const float* hp = h + ((size_t)s * Hn + head) * CC;
            acc0 += alpha * hp[lane];
            acc1 += alpha * hp[lane + 32];
        }
        float o0 = acc0 + bias[head*CC + lane];
        float o1 = acc1 + bias[head*CC + lane + 32];
        o0 = o0 > 0.f ? o0 : expm1f(o0);
        o1 = o1 > 0.f ? o1 : expm1f(o1);
        out[(size_t)w * CC + lane]      = o0;
        out[(size_t)w * CC + lane + 32] = o1;
    } else {
        // fallback: original verified 3-pass
        float m = -1e30f;
        for (int j = beg + lane; j < end; j += 32) {
            int s = g_csr[j];
            float e = a_s[s * Hn + head] + adn;
            e = e > 0.f ? e : 0.2f * e;
            m = fmaxf(m, e);
        }
        #pragma unroll
        for (int o = 16; o; o >>= 1) m = fmaxf(m, __shfl_xor_sync(FULL, m, o));
        float ssum = 0.f;
        for (int j = beg + lane; j < end; j += 32) {
            int s = g_csr[j];
            float e = a_s[s * Hn + head] + adn;
            e = e > 0.f ? e : 0.2f * e;
            ssum += __expf(e - m);
        }
        #pragma unroll
        for (int o = 16; o; o >>= 1) ssum += __shfl_xor_sync(FULL, ssum, o);
        float inv = 1.f / (ssum + 1e-16f);
        float acc0 = 0.f, acc1 = 0.f;
        for (int j = beg; j < end; ++j) {
            int s = g_csr[j];
            float e = a_s[s * Hn + head] + adn;
            e = e > 0.f ? e : 0.2f * e;
            float alpha = __expf(e - m) * inv;
            const float* hp = h + ((size_t)s * Hn + head) * CC;
            acc0 += alpha * hp[lane];
            acc1 += alpha * hp[lane + 32];
        }
        float o0 = acc0 + bias[head*CC + lane];
        float o1 = acc1 + bias[head*CC + lane + 32];
        o0 = o0 > 0.f ? o0 : expm1f(o0);
        o1 = o1 > 0.f ? o1 : expm1f(o1);
        out[(size_t)w * CC + lane]      = o0;
        out[(size_t)w * CC + lane + 32] = o1;
    }
}

// ---------------- global add pool (batch is sorted); 32-node chunks ----------------
__global__ void k_pool(const int* __restrict__ batch) {
    int c = threadIdx.x;
    int n0 = blockIdx.x * 32;
    int n1 = n0 + 32; if (n1 > NN) n1 = NN;
    if (n0 >= NN) return;
    float acc = 0.f;
    int cur = batch[n0];
    for (int i = n0; i < n1; i++) {
        int b = batch[i];
        if (b != cur) { atomicAdd(&g_pooled[cur*CC + c], acc); acc = 0.f; cur = b; }
        acc += g_out2[(size_t)i * CC + c];
    }
    atomicAdd(&g_pooled[cur*CC + c], acc);
}

// ---------------- head MLP + log_softmax ----------------
__global__ void k_head(const float* __restrict__ w1, const float* __restrict__ b1v,
                       const float* __restrict__ w2, const float* __restrict__ b2v,
                       float* __restrict__ out) {
    __shared__ float p[64], zs[64], lg[KK];
    int b = blockIdx.x, t = threadIdx.x;
    p[t] = g_pooled[b*CC + t];
    __syncthreads();
    float z = b1v[t];
    #pragma unroll 16
    for (int k = 0; k < 64; k++) z += p[k] * w1[k*64 + t];
    z = z > 0.f ? z : expm1f(z);
    zs[t] = z;
    __syncthreads();
    if (t < KK) {
        float l = b2v[t];
        #pragma unroll 16
        for (int k = 0; k < 64; k++) l += zs[k] * w2[k*KK + t];
        lg[t] = l;
    }
    __syncthreads();
    if (t < KK) {
        float m = -1e30f;
        #pragma unroll
        for (int k = 0; k < KK; k++) m = fmaxf(m, lg[k]);
        float s = 0.f;
        #pragma unroll
        for (int k = 0; k < KK; k++) s += expf(lg[k] - m);
        out[b*KK + t] = lg[t] - m - logf(s);
    }
}

// ---------------- launch ----------------
extern "C" void kernel_launch(void* const* d_in, const int* in_sizes, int n_in,
                              void* d_out, int out_size) {
    const float* x        = (const float*)d_in[0];
    const int*   ei       = (const int*)  d_in[1];
    const int*   batch    = (const int*)  d_in[2];
    const float* W1       = (const float*)d_in[3];
    const float* att_src1 = (const float*)d_in[4];
    const float* att_dst1 = (const float*)d_in[5];
    const float* b1       = (const float*)d_in[6];
    const float* W2       = (const float*)d_in[7];
    const float* att_src2 = (const float*)d_in[8];
    const float* att_dst2 = (const float*)d_in[9];
    const float* b2       = (const float*)d_in[10];
    const float* l1w      = (const float*)d_in[11];
    const float* l1b      = (const float*)d_in[12];
    const float* l2w      = (const float*)d_in[13];
    const float* l2b      = (const float*)d_in[14];
    float* out = (float*)d_out;

    const int* src = ei;
    const int* dst = ei + EE;

    void *p_h1, *p_out1, *p_h2, *p_out2, *p_as1, *p_ad1, *p_as2, *p_ad2;
    cudaGetSymbolAddress(&p_h1,  g_h1);
    cudaGetSymbolAddress(&p_out1, g_out1);
    cudaGetSymbolAddress(&p_h2,  g_h2);
    cudaGetSymbolAddress(&p_out2, g_out2);
    cudaGetSymbolAddress(&p_as1, g_as1);
    cudaGetSymbolAddress(&p_ad1, g_ad1);
    cudaGetSymbolAddress(&p_as2, g_as2);
    cudaGetSymbolAddress(&p_ad2, g_ad2);
    float* h1   = (float*)p_h1;
    float* out1 = (float*)p_out1;
    float* h2   = (float*)p_h2;
    float* out2 = (float*)p_out2;
    float* as1  = (float*)p_as1;
    float* ad1  = (float*)p_ad1;
    float* as2  = (float*)p_as2;
    float* ad2  = (float*)p_ad2;

    // order: k_attn_x lands in the profiled 4th launch slot (deps: k_prep only)
    k_init<<<(NN + 255)/256, 256>>>();
    k_count<<<(EE + 255)/256, 256>>>(dst);
    k_prep<<<(FF*HH + 255)/256, 256>>>(W1, att_src1, att_dst1);
    k_attn_x<<<(NN*HH + 255)/256, 256>>>(x, as1, ad1);          // <- profiled
    k_scan<<<1, 1024>>>();

    // GEMM1: [50000,128]@[128,512], register-staged BN=128 (measured best 135.7us)
    k_sgemm_t<128,128,16,8,8,2><<<dim3(HC/128, (NN + 127)/128), 256>>>(x, W1, h1, NN, HC, FF);

    k_scatter<<<(ETOT + 255)/256, 256>>>(src, dst);

    // Layer 1 aggregation (smem-cached)
    k_agg<<<(NN*HH + 7)/8, 256>>>(h1, as1, ad1, b1, out1, HH, NN*HH);

    // Layer 2: [50000,512]@[512,64] register-staged BN=64, 3 CTA/SM (measured best)
    k_sgemm_t<128,64,16,8,4,3><<<dim3(CC/64, (NN + 127)/128), 256>>>(out1, W2, h2, NN, CC, HC);
    k_attn<<<(NN + 7)/8, 256>>>(h2, att_src2, att_dst2, as2, ad2, 1, NN);
    k_agg<<<(NN + 7)/8, 256>>>(h2, as2, ad2, b2, out2, 1, NN);

    // Pool + head
    k_pool<<<(NN + 31)/32, 64>>>(batch);
    k_head<<<BB, 64>>>(l1w, l1b, l2w, l2b, out);
}